// round 11
// baseline (speedup 1.0000x reference)
#include <cuda_runtime.h>
#include <cuda_fp16.h>
#include <cstdint>
#include <math.h>

// Problem constants
#define BB    2
#define SS    2048
#define HH    2560
#define NHQ   8
#define NKV   4
#define DD    256
#define SWIN  1024
#define MROWS (BB*SS)          // 4096
#define QCOLS (NHQ*DD)         // 2048
#define KVCOLS (NKV*DD)        // 1024

// ---------------- scratch (allocation-free rule: device globals) ------------
__device__ float g_q [ (size_t)MROWS * QCOLS ];
__device__ float g_k [ (size_t)MROWS * KVCOLS ];
__device__ float g_v [ (size_t)MROWS * KVCOLS ];
__device__ int   g_work_ctr;

// split-fp16 operands
__device__ __half g_hid_h[(size_t)MROWS*HH],  g_hid_l[(size_t)MROWS*HH];
__device__ __half g_wq_h [(size_t)QCOLS*HH],  g_wq_l [(size_t)QCOLS*HH];
__device__ __half g_wk_h [(size_t)KVCOLS*HH], g_wk_l [(size_t)KVCOLS*HH];
__device__ __half g_wv_h [(size_t)KVCOLS*HH], g_wv_l [(size_t)KVCOLS*HH];
__device__ __half g_wo_h [(size_t)HH*QCOLS],  g_wo_l [(size_t)HH*QCOLS];
// post-rmsnorm/rope q/k (hi/lo) and v (hi only)
__device__ __half g_qh[(size_t)MROWS*QCOLS],  g_ql[(size_t)MROWS*QCOLS];
__device__ __half g_kh[(size_t)MROWS*KVCOLS], g_kl[(size_t)MROWS*KVCOLS];
__device__ __half g_vh[(size_t)MROWS*KVCOLS];
// attention output (hi only)
__device__ __half g_ao_h[(size_t)MROWS*QCOLS];

// ---------------- helpers ----------------------------------------------------
__device__ __forceinline__ uint32_t smem_u32(const void* p) {
    uint32_t a;
    asm("{ .reg .u64 t; cvta.to.shared.u64 t, %1; cvt.u32.u64 %0, t; }"
        : "=r"(a) : "l"(p));
    return a;
}
__device__ __forceinline__ void ldmatrix_x4(uint32_t* r, uint32_t addr) {
    asm volatile("ldmatrix.sync.aligned.m8n8.x4.shared.b16 {%0,%1,%2,%3}, [%4];"
                 : "=r"(r[0]), "=r"(r[1]), "=r"(r[2]), "=r"(r[3]) : "r"(addr));
}
__device__ __forceinline__ void ldmatrix_x4_t(uint32_t* r, uint32_t addr) {
    asm volatile("ldmatrix.sync.aligned.m8n8.x4.trans.shared.b16 {%0,%1,%2,%3}, [%4];"
                 : "=r"(r[0]), "=r"(r[1]), "=r"(r[2]), "=r"(r[3]) : "r"(addr));
}
__device__ __forceinline__ void mma_f16(float* d, const uint32_t* a,
                                        uint32_t b0, uint32_t b1) {
    asm volatile(
        "mma.sync.aligned.m16n8k16.row.col.f32.f16.f16.f32 "
        "{%0,%1,%2,%3}, {%4,%5,%6,%7}, {%8,%9}, {%0,%1,%2,%3};"
        : "+f"(d[0]), "+f"(d[1]), "+f"(d[2]), "+f"(d[3])
        : "r"(a[0]), "r"(a[1]), "r"(a[2]), "r"(a[3]), "r"(b0), "r"(b1));
}
__device__ __forceinline__ void cp_async16(uint32_t saddr, const void* gaddr) {
    asm volatile("cp.async.cg.shared.global [%0], [%1], 16;"
                 :: "r"(saddr), "l"(gaddr));
}
__device__ __forceinline__ uint32_t pack_h2(float a, float b) {
    __half2 t; t.x = __float2half(a); t.y = __float2half(b);
    return *(uint32_t*)&t;
}

// ---------------------------------------------------------------------------
// split fp32 -> (hi, lo) fp16
// ---------------------------------------------------------------------------
__global__ void split_kernel(const float* __restrict__ src,
                             __half* __restrict__ hi,
                             __half* __restrict__ lo, int n4)
{
    int i = blockIdx.x * blockDim.x + threadIdx.x;
    if (i >= n4) return;
    float4 v = ((const float4*)src)[i];
    __half hx = __float2half(v.x), hy = __float2half(v.y);
    __half hz = __float2half(v.z), hw = __float2half(v.w);
    __half lx = __float2half(v.x - __half2float(hx));
    __half ly = __float2half(v.y - __half2float(hy));
    __half lz = __float2half(v.z - __half2float(hz));
    __half lw = __float2half(v.w - __half2float(hw));
    __half2 h01; h01.x = hx; h01.y = hy;
    __half2 h23; h23.x = hz; h23.y = hw;
    __half2 l01; l01.x = lx; l01.y = ly;
    __half2 l23; l23.x = lz; l23.y = lw;
    ((__half2*)hi)[2*i]   = h01;
    ((__half2*)hi)[2*i+1] = h23;
    ((__half2*)lo)[2*i]   = l01;
    ((__half2*)lo)[2*i+1] = l23;
}

// ---------------------------------------------------------------------------
// Fused QKV projection, 3-pass split-fp16 HMMA, 3-STAGE cp.async pipeline
// (two chunks in flight hide L2 latency). Single launch, 32x32 grid.
// ---------------------------------------------------------------------------
#define PADK   40
#define TILE_B (128 * PADK * 2)
#define STAGE3_B (4 * TILE_B)       // 40960
#define QKV_SMEM (3 * STAGE3_B)     // 122880

__global__ void __launch_bounds__(256) gemm_qkv(
    const __half* __restrict__ Ah, const __half* __restrict__ Al,
    const __half* __restrict__ wqh, const __half* __restrict__ wql,
    const __half* __restrict__ wkh, const __half* __restrict__ wkl,
    const __half* __restrict__ wvh, const __half* __restrict__ wvl,
    float* __restrict__ qout, float* __restrict__ kout, float* __restrict__ vout)
{
    extern __shared__ char smem[];
    const uint32_t sbase = smem_u32(smem);
    const int K = HH;

    const int tid  = threadIdx.x;
    const int wid  = tid >> 5, lane = tid & 31;
    const int wm   = wid >> 2;
    const int wn   = wid & 3;
    const int m0   = blockIdx.y * 128;
    const int n0g  = blockIdx.x * 128;

    const __half *Bh, *Bl;
    float* C;
    int n0, NN;
    if (n0g < QCOLS)              { Bh = wqh; Bl = wql; C = qout; n0 = n0g;          NN = QCOLS; }
    else if (n0g < QCOLS+KVCOLS)  { Bh = wkh; Bl = wkl; C = kout; n0 = n0g - QCOLS;  NN = KVCOLS; }
    else                          { Bh = wvh; Bl = wvl; C = vout; n0 = n0g - 3072;   NN = KVCOLS; }

    const __half* gb[4] = {
        Ah + (size_t)m0 * K, Al + (size_t)m0 * K,
        Bh + (size_t)n0 * K, Bl + (size_t)n0 * K };

    const int NC = K >> 5;   // 80

#define ISSUE3(c, s) do {                                                     \
    _Pragma("unroll")                                                         \
    for (int i = 0; i < 8; i++) {                                             \
        int e    = tid + i * 256;                                             \
        int t    = e >> 9;                                                    \
        int rem  = e & 511;                                                   \
        int row  = rem >> 2;                                                  \
        int c16  = rem & 3;                                                   \
        uint32_t sa = sbase + (s) * STAGE3_B + t * TILE_B + row * (PADK*2) + c16 * 16; \
        cp_async16(sa, gb[t] + (size_t)row * K + (c) * 32 + c16 * 8);         \
    }                                                                         \
    asm volatile("cp.async.commit_group;" ::: "memory");                      \
} while (0)

    float acc[4][4][4];
#pragma unroll
    for (int i = 0; i < 4; i++)
#pragma unroll
        for (int j = 0; j < 4; j++)
#pragma unroll
            for (int r = 0; r < 4; r++) acc[i][j][r] = 0.f;

    const uint32_t a_off = (uint32_t)((lane & 15) * (PADK*2) + (lane >> 4) * 16);
    const uint32_t b_off = (uint32_t)(((lane & 7) + ((lane >> 4) << 3)) * (PADK*2)
                                      + ((lane >> 3) & 1) * 16);

    ISSUE3(0, 0);
    ISSUE3(1, 1);

    for (int c = 0; c < NC; c++) {
        const int s = c % 3;
        if (c + 2 < NC) {
            ISSUE3(c + 2, (c + 2) % 3);
            asm volatile("cp.async.wait_group 2;" ::: "memory");
        } else if (c + 1 < NC) {
            asm volatile("cp.async.wait_group 1;" ::: "memory");
        } else {
            asm volatile("cp.async.wait_group 0;" ::: "memory");
        }
        __syncthreads();

        const uint32_t sAh = sbase + s * STAGE3_B;
        const uint32_t sAl = sAh + TILE_B;
        const uint32_t sBh = sAh + 2 * TILE_B;
        const uint32_t sBl = sAh + 3 * TILE_B;

#pragma unroll
        for (int ks = 0; ks < 2; ks++) {
            const uint32_t kbyte = (uint32_t)(ks * 32);

            uint32_t ah[4][4], al[4][4];
#pragma unroll
            for (int i = 0; i < 4; i++) {
                const uint32_t ro = (uint32_t)((wm * 64 + i * 16) * (PADK*2)) + kbyte;
                ldmatrix_x4(ah[i], sAh + ro + a_off);
                ldmatrix_x4(al[i], sAl + ro + a_off);
            }
            uint32_t bh[2][4], bl[2][4];
#pragma unroll
            for (int p = 0; p < 2; p++) {
                const uint32_t ro = (uint32_t)((wn * 32 + p * 16) * (PADK*2)) + kbyte;
                ldmatrix_x4(bh[p], sBh + ro + b_off);
                ldmatrix_x4(bl[p], sBl + ro + b_off);
            }
#pragma unroll
            for (int i = 0; i < 4; i++)
#pragma unroll
                for (int j = 0; j < 4; j++) {
                    const int p = j >> 1, u = (j & 1) * 2;
                    mma_f16(acc[i][j], ah[i], bh[p][u], bh[p][u+1]);
                    mma_f16(acc[i][j], ah[i], bl[p][u], bl[p][u+1]);
                    mma_f16(acc[i][j], al[i], bh[p][u], bh[p][u+1]);
                }
        }
        __syncthreads();
    }
#undef ISSUE3

    const int rbase = m0 + wm * 64 + (lane >> 2);
    const int cbase = n0 + wn * 32 + (lane & 3) * 2;
#pragma unroll
    for (int i = 0; i < 4; i++)
#pragma unroll
        for (int j = 0; j < 4; j++) {
            float* p0 = C + (size_t)(rbase + i * 16) * NN + cbase + j * 8;
            float* p1 = p0 + 8 * (size_t)NN;
            *(float2*)p0 = make_float2(acc[i][j][0], acc[i][j][1]);
            *(float2*)p1 = make_float2(acc[i][j][2], acc[i][j][3]);
        }
}

// ---------------------------------------------------------------------------
// Output projection, 1-PASS fp16 HMMA (out = ao_h * Wo_h^T), 3-stage pipeline.
// Dropped Wo_l correction: independent ~2.4e-4 term, inside error budget.
// ---------------------------------------------------------------------------
#define STAGE1_B (2 * TILE_B)       // 20480
#define WO_SMEM (3 * STAGE1_B)      // 61440

__global__ void __launch_bounds__(256) gemm_wo(
    const __half* __restrict__ Ah,
    const __half* __restrict__ Bh,
    float* __restrict__ C)
{
    extern __shared__ char smem[];
    const uint32_t sbase = smem_u32(smem);
    const int K = QCOLS, NN = HH;

    const int tid  = threadIdx.x;
    const int wid  = tid >> 5, lane = tid & 31;
    const int wm   = wid >> 2;
    const int wn   = wid & 3;
    const int m0   = blockIdx.y * 128, n0 = blockIdx.x * 128;

    const __half* gb[2] = { Ah + (size_t)m0 * K, Bh + (size_t)n0 * K };

    const int NC = K >> 5;   // 64

#define ISSUE1(c, s) do {                                                     \
    _Pragma("unroll")                                                         \
    for (int i = 0; i < 4; i++) {                                             \
        int e    = tid + i * 256;                                             \
        int t    = e >> 9;                                                    \
        int rem  = e & 511;                                                   \
        int row  = rem >> 2;                                                  \
        int c16  = rem & 3;                                                   \
        uint32_t sa = sbase + (s) * STAGE1_B + t * TILE_B + row * (PADK*2) + c16 * 16; \
        cp_async16(sa, gb[t] + (size_t)row * K + (c) * 32 + c16 * 8);         \
    }                                                                         \
    asm volatile("cp.async.commit_group;" ::: "memory");                      \
} while (0)

    float acc[4][4][4];
#pragma unroll
    for (int i = 0; i < 4; i++)
#pragma unroll
        for (int j = 0; j < 4; j++)
#pragma unroll
            for (int r = 0; r < 4; r++) acc[i][j][r] = 0.f;

    const uint32_t a_off = (uint32_t)((lane & 15) * (PADK*2) + (lane >> 4) * 16);
    const uint32_t b_off = (uint32_t)(((lane & 7) + ((lane >> 4) << 3)) * (PADK*2)
                                      + ((lane >> 3) & 1) * 16);

    ISSUE1(0, 0);
    ISSUE1(1, 1);

    for (int c = 0; c < NC; c++) {
        const int s = c % 3;
        if (c + 2 < NC) {
            ISSUE1(c + 2, (c + 2) % 3);
            asm volatile("cp.async.wait_group 2;" ::: "memory");
        } else if (c + 1 < NC) {
            asm volatile("cp.async.wait_group 1;" ::: "memory");
        } else {
            asm volatile("cp.async.wait_group 0;" ::: "memory");
        }
        __syncthreads();

        const uint32_t sAh = sbase + s * STAGE1_B;
        const uint32_t sBh = sAh + TILE_B;

#pragma unroll
        for (int ks = 0; ks < 2; ks++) {
            const uint32_t kbyte = (uint32_t)(ks * 32);

            uint32_t ah[4][4];
#pragma unroll
            for (int i = 0; i < 4; i++) {
                const uint32_t ro = (uint32_t)((wm * 64 + i * 16) * (PADK*2)) + kbyte;
                ldmatrix_x4(ah[i], sAh + ro + a_off);
            }
            uint32_t bh[2][4];
#pragma unroll
            for (int p = 0; p < 2; p++) {
                const uint32_t ro = (uint32_t)((wn * 32 + p * 16) * (PADK*2)) + kbyte;
                ldmatrix_x4(bh[p], sBh + ro + b_off);
            }
#pragma unroll
            for (int i = 0; i < 4; i++)
#pragma unroll
                for (int j = 0; j < 4; j++) {
                    const int p = j >> 1, u = (j & 1) * 2;
                    mma_f16(acc[i][j], ah[i], bh[p][u], bh[p][u+1]);
                }
        }
        __syncthreads();
    }
#undef ISSUE1

    const int rbase = m0 + wm * 64 + (lane >> 2);
    const int cbase = n0 + wn * 32 + (lane & 3) * 2;
#pragma unroll
    for (int i = 0; i < 4; i++)
#pragma unroll
        for (int j = 0; j < 4; j++) {
            float* p0 = C + (size_t)(rbase + i * 16) * NN + cbase + j * 8;
            float* p1 = p0 + 8 * (size_t)NN;
            *(float2*)p0 = make_float2(acc[i][j][0], acc[i][j][1]);
            *(float2*)p1 = make_float2(acc[i][j][2], acc[i][j][3]);
        }
}

// ---------------------------------------------------------------------------
// RMSNorm (+ optional weight) + RoPE — warp-per-(row,head), float4 I/O,
// shuffle-only reduction. Also resets the attention work counter.
// ---------------------------------------------------------------------------
__global__ void __launch_bounds__(256) rmsrope_kernel(
    const float* __restrict__ cosb, const float* __restrict__ sinb,
    const float* __restrict__ qw,  const float* __restrict__ kw)
{
    if (blockIdx.x == 0 && threadIdx.x == 0) g_work_ctr = 0;

    const int gw   = blockIdx.x * 8 + (threadIdx.x >> 5);
    const int row  = gw >> 4;
    const int part = gw & 15;
    const int lane = threadIdx.x & 31;
    const int d0   = lane * 4;

    const float* ptr;
    __half *hp, *lp = nullptr;
    const float* w = nullptr;
    bool do_rope = true;
    if (part < 8) {
        size_t off = (size_t)row * QCOLS + part * DD;
        ptr = g_q + off; hp = g_qh + off; lp = g_ql + off; w = qw;
    } else if (part < 12) {
        size_t off = (size_t)row * KVCOLS + (part - 8) * DD;
        ptr = g_k + off; hp = g_kh + off; lp = g_kl + off; w = kw;
    } else {
        size_t off = (size_t)row * KVCOLS + (part - 12) * DD;
        ptr = g_v + off; hp = g_vh + off; do_rope = false;
    }

    float4 x1 = *(const float4*)(ptr + d0);
    float4 x2 = *(const float4*)(ptr + 128 + d0);
    float ss = x1.x*x1.x + x1.y*x1.y + x1.z*x1.z + x1.w*x1.w
             + x2.x*x2.x + x2.y*x2.y + x2.z*x2.z + x2.w*x2.w;
#pragma unroll
    for (int o = 16; o; o >>= 1) ss += __shfl_xor_sync(0xffffffffu, ss, o);
    const float inv = rsqrtf(ss * (1.0f / DD) + 1e-6f);

    float y1[4] = { x1.x*inv, x1.y*inv, x1.z*inv, x1.w*inv };
    float y2[4] = { x2.x*inv, x2.y*inv, x2.z*inv, x2.w*inv };

    if (w) {
        float4 w1 = *(const float4*)(w + d0);
        float4 w2 = *(const float4*)(w + 128 + d0);
        y1[0] *= 1.f + w1.x; y1[1] *= 1.f + w1.y;
        y1[2] *= 1.f + w1.z; y1[3] *= 1.f + w1.w;
        y2[0] *= 1.f + w2.x; y2[1] *= 1.f + w2.y;
        y2[2] *= 1.f + w2.z; y2[3] *= 1.f + w2.w;
    }

    float o1[4], o2[4];
    if (do_rope) {
        const int s = row & (SS - 1);
        const float* cb = cosb + (size_t)s * DD;
        const float* sb = sinb + (size_t)s * DD;
        float4 c1 = *(const float4*)(cb + d0);
        float4 s1 = *(const float4*)(sb + d0);
        float4 c2 = *(const float4*)(cb + 128 + d0);
        float4 s2 = *(const float4*)(sb + 128 + d0);
        o1[0] = y1[0]*c1.x - y2[0]*s1.x;  o1[1] = y1[1]*c1.y - y2[1]*s1.y;
        o1[2] = y1[2]*c1.z - y2[2]*s1.z;  o1[3] = y1[3]*c1.w - y2[3]*s1.w;
        o2[0] = y2[0]*c2.x + y1[0]*s2.x;  o2[1] = y2[1]*c2.y + y1[1]*s2.y;
        o2[2] = y2[2]*c2.z + y1[2]*s2.z;  o2[3] = y2[3]*c2.w + y1[3]*s2.w;
    } else {
#pragma unroll
        for (int i = 0; i < 4; i++) { o1[i] = y1[i]; o2[i] = y2[i]; }
    }

    uint2 h1, h2;
    h1.x = pack_h2(o1[0], o1[1]); h1.y = pack_h2(o1[2], o1[3]);
    h2.x = pack_h2(o2[0], o2[1]); h2.y = pack_h2(o2[2], o2[3]);
    *(uint2*)(hp + d0)       = h1;
    *(uint2*)(hp + 128 + d0) = h2;
    if (lp) {
        __half q10 = __float2half(o1[0]), q11 = __float2half(o1[1]);
        __half q12 = __float2half(o1[2]), q13 = __float2half(o1[3]);
        __half q20 = __float2half(o2[0]), q21 = __float2half(o2[1]);
        __half q22 = __float2half(o2[2]), q23 = __float2half(o2[3]);
        uint2 l1, l2;
        l1.x = pack_h2(o1[0] - __half2float(q10), o1[1] - __half2float(q11));
        l1.y = pack_h2(o1[2] - __half2float(q12), o1[3] - __half2float(q13));
        l2.x = pack_h2(o2[0] - __half2float(q20), o2[1] - __half2float(q21));
        l2.y = pack_h2(o2[2] - __half2float(q22), o2[3] - __half2float(q23));
        *(uint2*)(lp + d0)       = l1;
        *(uint2*)(lp + 128 + d0) = l2;
    }
}

// ---------------------------------------------------------------------------
// HMMA split-fp16 sliding-window flash attention — persistent work queue.
// QK^T: 3-pass. PV: single pass (Ph * Vh).
// ---------------------------------------------------------------------------
#define QSTR 528
#define QTILE (128 * QSTR)
#define KTILE (64 * QSTR)
#define ATT_SMEM (2*QTILE + 2*KTILE) // 202752
#define NWORK (16 * NHQ * BB)        // 256 work items

__global__ void __launch_bounds__(256, 1) attn_hmma()
{
    extern __shared__ char smem[];
    const uint32_t sb   = smem_u32(smem);
    const uint32_t qh_s = sb;
    const uint32_t ql_s = sb + QTILE;
    const uint32_t k0_s = sb + 2 * QTILE;    // slot0: K-hi
    const uint32_t k1_s = k0_s + KTILE;      // slot1: K-lo, then V

    const int tid  = threadIdx.x;
    const int wid  = tid >> 5, lane = tid & 31;
    const int wrow = wid * 16;

    __shared__ int s_item;

    const uint32_t a_off = (uint32_t)((wrow + (lane & 15)) * QSTR + (lane >> 4) * 16);
    const uint32_t b_off = (uint32_t)(((lane & 7) + ((lane >> 4) << 3)) * QSTR
                                      + ((lane >> 3) & 1) * 16);
    const uint32_t v_off = (uint32_t)((lane & 15) * QSTR + (lane >> 4) * 16);
    const int lg = lane >> 2;
    const int lc = (lane & 3) * 2;

    for (;;) {
        __syncthreads();
        if (tid == 0) s_item = atomicAdd(&g_work_ctr, 1);
        __syncthreads();
        const int item = s_item;
        if (item >= NWORK) break;

        const int rrr  = item >> 4;
        const int bh   = item & 15;
        const int qblk = 15 - rrr;
        const int h    = bh & 7;
        const int b    = bh >> 3;
        const int kvh  = h >> 1;
        const int qs   = qblk * 128;

        // ---- Q load (hi & lo) ----
        {
            const __half* qsrc[2] = {
                g_qh + (size_t)(b*SS + qs) * QCOLS + h * DD,
                g_ql + (size_t)(b*SS + qs) * QCOLS + h * DD };
#pragma unroll
            for (int i = 0; i < 32; i++) {
                int e = tid + i * 256;
                int arr = e >> 12;
                int rem = e & 4095;
                int row = rem >> 5, c16 = rem & 31;
                cp_async16((arr ? ql_s : qh_s) + row * QSTR + c16 * 16,
                           qsrc[arr] + (size_t)row * QCOLS + c16 * 8);
            }
            asm volatile("cp.async.commit_group;" ::: "memory");
        }

        float out[32][4];
#pragma unroll
        for (int nt = 0; nt < 32; nt++)
#pragma unroll
            for (int r = 0; r < 4; r++) out[nt][r] = 0.f;
        float mrow[2] = {-1e30f, -1e30f};
        float lrow[2] = {0.f, 0.f};

        const __half* khg = g_kh + (size_t)(b*SS) * KVCOLS + kvh * DD;
        const __half* klg = g_kl + (size_t)(b*SS) * KVCOLS + kvh * DD;
        const __half* vhg = g_vh + (size_t)(b*SS) * KVCOLS + kvh * DD;

        int ksmin = qs - (SWIN - 1);
        if (ksmin < 0) ksmin = 0;
        const int t0 = ksmin >> 6;
        const int t1 = (qs + 127) >> 6;

#define LOAD_TILE(dst, src, ks_) do {                                          \
    _Pragma("unroll")                                                          \
    for (int i = 0; i < 8; i++) {                                              \
        int e = tid + i * 256;                                                 \
        int row = e >> 5, c16 = e & 31;                                        \
        cp_async16((dst) + row * QSTR + c16 * 16,                              \
                   (src) + (size_t)((ks_) + row) * KVCOLS + c16 * 8);          \
    }                                                                          \
    asm volatile("cp.async.commit_group;" ::: "memory");                       \
} while (0)

        LOAD_TILE(k0_s, khg, t0 << 6);
        LOAD_TILE(k1_s, klg, t0 << 6);

        for (int kt = t0; kt <= t1; kt++) {
            const int ks = kt << 6;
            const bool more = (kt < t1);

            asm volatile("cp.async.wait_group 0;" ::: "memory");
            __syncthreads();

            // ---- S = Q K^T (3-pass, fp32 acc) ----
            float sacc[8][4];
#pragma unroll
            for (int j = 0; j < 8; j++)
#pragma unroll
                for (int r = 0; r < 4; r++) sacc[j][r] = 0.f;

#pragma unroll
            for (int ks16 = 0; ks16 < 16; ks16++) {
                uint32_t qf_h[4], qf_l[4];
                ldmatrix_x4(qf_h, qh_s + a_off + ks16 * 32);
                ldmatrix_x4(qf_l, ql_s + a_off + ks16 * 32);
#pragma unroll
                for (int jp = 0; jp < 4; jp++) {
                    uint32_t kf_h[4], kf_l[4];
                    const uint32_t ro = (uint32_t)(jp * 16 * QSTR) + ks16 * 32;
                    ldmatrix_x4(kf_h, k0_s + ro + b_off);
                    ldmatrix_x4(kf_l, k1_s + ro + b_off);
#pragma unroll
                    for (int u = 0; u < 2; u++) {
                        const int j = jp * 2 + u;
                        mma_f16(sacc[j], qf_h, kf_h[u*2], kf_h[u*2+1]);
                        mma_f16(sacc[j], qf_h, kf_l[u*2], kf_l[u*2+1]);
                        mma_f16(sacc[j], qf_l, kf_h[u*2], kf_h[u*2+1]);
                    }
                }
            }
            __syncthreads();

            LOAD_TILE(k1_s, vhg, ks);
            if (more) LOAD_TILE(k0_s, khg, ks + 64);

            // ---- mask + online softmax (warp-local) ----
            uint32_t ph[8][2];
#pragma unroll
            for (int g = 0; g < 2; g++) {
                const int qi = qs + wrow + lg + g * 8;
                float mloc = -1e30f;
#pragma unroll
                for (int j = 0; j < 8; j++)
#pragma unroll
                    for (int e = 0; e < 2; e++) {
                        const int kj = ks + j * 8 + lc + e;
                        float s = sacc[j][g*2+e];
                        if (kj > qi || kj <= qi - SWIN) s = -1e30f;
                        sacc[j][g*2+e] = s;
                        mloc = fmaxf(mloc, s);
                    }
                mloc = fmaxf(mloc, __shfl_xor_sync(0xffffffffu, mloc, 1));
                mloc = fmaxf(mloc, __shfl_xor_sync(0xffffffffu, mloc, 2));
                const float mnew = fmaxf(mrow[g], mloc);
                const float corr = __expf(mrow[g] - mnew);
                float ls = 0.f;
#pragma unroll
                for (int j = 0; j < 8; j++)
#pragma unroll
                    for (int e = 0; e < 2; e++) {
                        float s = sacc[j][g*2+e];
                        float p = (s <= -1e29f) ? 0.f : __expf(s - mnew);
                        sacc[j][g*2+e] = p;
                        ls += p;
                    }
                ls += __shfl_xor_sync(0xffffffffu, ls, 1);
                ls += __shfl_xor_sync(0xffffffffu, ls, 2);
                lrow[g] = lrow[g] * corr + ls;
                mrow[g] = mnew;
#pragma unroll
                for (int nt = 0; nt < 32; nt++) {
                    out[nt][g*2+0] *= corr;
                    out[nt][g*2+1] *= corr;
                }
            }
            // pack P -> fp16 A-fragments (hi only)
#pragma unroll
            for (int j = 0; j < 8; j++)
#pragma unroll
                for (int g = 0; g < 2; g++)
                    ph[j][g] = pack_h2(sacc[j][g*2+0], sacc[j][g*2+1]);

            if (more) { asm volatile("cp.async.wait_group 1;" ::: "memory"); }
            else      { asm volatile("cp.async.wait_group 0;" ::: "memory"); }
            __syncthreads();

            // ---- O += P V (single pass; V in slot1) ----
#pragma unroll
            for (int s = 0; s < 4; s++) {
                uint32_t aph[4] = { ph[2*s][0], ph[2*s][1], ph[2*s+1][0], ph[2*s+1][1] };
                const uint32_t krow = (uint32_t)(s * 16 * QSTR);
#pragma unroll
                for (int np = 0; np < 16; np++) {
                    uint32_t vf_h[4];
                    const uint32_t vo = krow + (uint32_t)(np * 32) + v_off;
                    ldmatrix_x4_t(vf_h, k1_s + vo);
#pragma unroll
                    for (int u = 0; u < 2; u++) {
                        const int nt = np * 2 + u;
                        mma_f16(out[nt], aph, vf_h[u*2], vf_h[u*2+1]);
                    }
                }
            }
            __syncthreads();

            if (more) LOAD_TILE(k1_s, klg, ks + 64);
        }
#undef LOAD_TILE

        // ---- epilogue ----
#pragma unroll
        for (int g = 0; g < 2; g++) {
            const float inv = 1.0f / lrow[g];
            const int row = qs + wrow + lg + g * 8;
            __half* oh = g_ao_h + (size_t)(b*SS + row) * QCOLS + h * DD + lc;
#pragma unroll
            for (int nt = 0; nt < 32; nt++) {
                *(uint32_t*)(oh + nt*8) = pack_h2(out[nt][g*2+0] * inv,
                                                  out[nt][g*2+1] * inv);
            }
        }
    }
}

// ---------------------------------------------------------------------------
extern "C" void kernel_launch(void* const* d_in, const int* in_sizes, int n_in,
                              void* d_out, int out_size)
{
    (void)in_sizes; (void)n_in; (void)out_size;
    const float* hidden = (const float*)d_in[0];
    // d_in[1] = attention_mask — analytic, unused
    const float* cosb = (const float*)d_in[2];
    const float* sinb = (const float*)d_in[3];
    const float* Wq = (const float*)d_in[4];
    const float* Wk = (const float*)d_in[5];
    const float* Wv = (const float*)d_in[6];
    const float* Wo = (const float*)d_in[7];
    const float* qw = (const float*)d_in[8];
    const float* kw = (const float*)d_in[9];
    float* out = (float*)d_out;

    float *qp, *kp, *vp;
    cudaGetSymbolAddress((void**)&qp, g_q);
    cudaGetSymbolAddress((void**)&kp, g_k);
    cudaGetSymbolAddress((void**)&vp, g_v);
    __half *hid_h, *hid_l, *wq_h, *wq_l, *wk_h, *wk_l, *wv_h, *wv_l,
           *wo_h, *wo_l, *ao_h;
    cudaGetSymbolAddress((void**)&hid_h, g_hid_h);
    cudaGetSymbolAddress((void**)&hid_l, g_hid_l);
    cudaGetSymbolAddress((void**)&wq_h,  g_wq_h);
    cudaGetSymbolAddress((void**)&wq_l,  g_wq_l);
    cudaGetSymbolAddress((void**)&wk_h,  g_wk_h);
    cudaGetSymbolAddress((void**)&wk_l,  g_wk_l);
    cudaGetSymbolAddress((void**)&wv_h,  g_wv_h);
    cudaGetSymbolAddress((void**)&wv_l,  g_wv_l);
    cudaGetSymbolAddress((void**)&wo_h,  g_wo_h);
    cudaGetSymbolAddress((void**)&wo_l,  g_wo_l);
    cudaGetSymbolAddress((void**)&ao_h,  g_ao_h);

    cudaFuncSetAttribute(gemm_qkv, cudaFuncAttributeMaxDynamicSharedMemorySize, QKV_SMEM);
    cudaFuncSetAttribute(gemm_wo,  cudaFuncAttributeMaxDynamicSharedMemorySize, WO_SMEM);
    cudaFuncSetAttribute(attn_hmma, cudaFuncAttributeMaxDynamicSharedMemorySize, ATT_SMEM);

    // 0) split fp32 -> fp16 hi/lo
    {
        int n4;
        n4 = (int)((size_t)MROWS * HH / 4);
        split_kernel<<<(n4 + 255) / 256, 256>>>(hidden, hid_h, hid_l, n4);
        n4 = (int)((size_t)QCOLS * HH / 4);
        split_kernel<<<(n4 + 255) / 256, 256>>>(Wq, wq_h, wq_l, n4);
        n4 = (int)((size_t)KVCOLS * HH / 4);
        split_kernel<<<(n4 + 255) / 256, 256>>>(Wk, wk_h, wk_l, n4);
        split_kernel<<<(n4 + 255) / 256, 256>>>(Wv, wv_h, wv_l, n4);
        n4 = (int)((size_t)HH * QCOLS / 4);
        split_kernel<<<(n4 + 255) / 256, 256>>>(Wo, wo_h, wo_l, n4);
    }

    // 1) fused QKV projection (3-pass, 3-stage pipeline)
    gemm_qkv<<<dim3(32, 32), 256, QKV_SMEM>>>(
        hid_h, hid_l, wq_h, wq_l, wk_h, wk_l, wv_h, wv_l, qp, kp, vp);

    // 2) RMSNorm + RoPE (warp-per-row) -> fp16 hi/lo; resets work counter
    rmsrope_kernel<<<MROWS * 16 / 8, 256>>>(cosb, sinb, qw, kw);

    // 3) persistent HMMA sliding-window flash attention -> fp16 ao
    attn_hmma<<<152, 256, ATT_SMEM>>>();

    // 4) output projection (1-pass, 3-stage pipeline) -> fp32 d_out
    gemm_wo<<<dim3(HH/128, MROWS/128), 256, WO_SMEM>>>(ao_h, wo_h, out);
}

// round 12
// speedup vs baseline: 1.1783x; 1.1783x over previous
#include <cuda_runtime.h>
#include <cuda_fp16.h>
#include <cstdint>
#include <math.h>

// Problem constants
#define BB    2
#define SS    2048
#define HH    2560
#define NHQ   8
#define NKV   4
#define DD    256
#define SWIN  1024
#define MROWS (BB*SS)          // 4096
#define QCOLS (NHQ*DD)         // 2048
#define KVCOLS (NKV*DD)        // 1024

// ---------------- scratch (allocation-free rule: device globals) ------------
__device__ float g_q [ (size_t)MROWS * QCOLS ];
__device__ float g_k [ (size_t)MROWS * KVCOLS ];
__device__ float g_v [ (size_t)MROWS * KVCOLS ];
__device__ int   g_work_ctr;

// split-fp16 operands
__device__ __half g_hid_h[(size_t)MROWS*HH],  g_hid_l[(size_t)MROWS*HH];
__device__ __half g_wq_h [(size_t)QCOLS*HH],  g_wq_l [(size_t)QCOLS*HH];
__device__ __half g_wk_h [(size_t)KVCOLS*HH], g_wk_l [(size_t)KVCOLS*HH];
__device__ __half g_wv_h [(size_t)KVCOLS*HH], g_wv_l [(size_t)KVCOLS*HH];
__device__ __half g_wo_h [(size_t)HH*QCOLS],  g_wo_l [(size_t)HH*QCOLS];
// post-rmsnorm/rope q/k (hi/lo) and v (hi only)
__device__ __half g_qh[(size_t)MROWS*QCOLS],  g_ql[(size_t)MROWS*QCOLS];
__device__ __half g_kh[(size_t)MROWS*KVCOLS], g_kl[(size_t)MROWS*KVCOLS];
__device__ __half g_vh[(size_t)MROWS*KVCOLS];
// attention output (hi only)
__device__ __half g_ao_h[(size_t)MROWS*QCOLS];

// ---------------- helpers ----------------------------------------------------
__device__ __forceinline__ uint32_t smem_u32(const void* p) {
    uint32_t a;
    asm("{ .reg .u64 t; cvta.to.shared.u64 t, %1; cvt.u32.u64 %0, t; }"
        : "=r"(a) : "l"(p));
    return a;
}
__device__ __forceinline__ void ldmatrix_x4(uint32_t* r, uint32_t addr) {
    asm volatile("ldmatrix.sync.aligned.m8n8.x4.shared.b16 {%0,%1,%2,%3}, [%4];"
                 : "=r"(r[0]), "=r"(r[1]), "=r"(r[2]), "=r"(r[3]) : "r"(addr));
}
__device__ __forceinline__ void ldmatrix_x4_t(uint32_t* r, uint32_t addr) {
    asm volatile("ldmatrix.sync.aligned.m8n8.x4.trans.shared.b16 {%0,%1,%2,%3}, [%4];"
                 : "=r"(r[0]), "=r"(r[1]), "=r"(r[2]), "=r"(r[3]) : "r"(addr));
}
__device__ __forceinline__ void mma_f16(float* d, const uint32_t* a,
                                        uint32_t b0, uint32_t b1) {
    asm volatile(
        "mma.sync.aligned.m16n8k16.row.col.f32.f16.f16.f32 "
        "{%0,%1,%2,%3}, {%4,%5,%6,%7}, {%8,%9}, {%0,%1,%2,%3};"
        : "+f"(d[0]), "+f"(d[1]), "+f"(d[2]), "+f"(d[3])
        : "r"(a[0]), "r"(a[1]), "r"(a[2]), "r"(a[3]), "r"(b0), "r"(b1));
}
__device__ __forceinline__ void cp_async16(uint32_t saddr, const void* gaddr) {
    asm volatile("cp.async.cg.shared.global [%0], [%1], 16;"
                 :: "r"(saddr), "l"(gaddr));
}
__device__ __forceinline__ uint32_t pack_h2(float a, float b) {
    __half2 t; t.x = __float2half(a); t.y = __float2half(b);
    return *(uint32_t*)&t;
}

// ---------------------------------------------------------------------------
// split fp32 -> (hi, lo) fp16
// ---------------------------------------------------------------------------
__global__ void split_kernel(const float* __restrict__ src,
                             __half* __restrict__ hi,
                             __half* __restrict__ lo, int n4)
{
    int i = blockIdx.x * blockDim.x + threadIdx.x;
    if (i >= n4) return;
    float4 v = ((const float4*)src)[i];
    __half hx = __float2half(v.x), hy = __float2half(v.y);
    __half hz = __float2half(v.z), hw = __float2half(v.w);
    __half lx = __float2half(v.x - __half2float(hx));
    __half ly = __float2half(v.y - __half2float(hy));
    __half lz = __float2half(v.z - __half2float(hz));
    __half lw = __float2half(v.w - __half2float(hw));
    __half2 h01; h01.x = hx; h01.y = hy;
    __half2 h23; h23.x = hz; h23.y = hw;
    __half2 l01; l01.x = lx; l01.y = ly;
    __half2 l23; l23.x = lz; l23.y = lw;
    ((__half2*)hi)[2*i]   = h01;
    ((__half2*)hi)[2*i+1] = h23;
    ((__half2*)lo)[2*i]   = l01;
    ((__half2*)lo)[2*i+1] = l23;
}

// ---------------------------------------------------------------------------
// Fused QKV projection, 3-pass split-fp16 HMMA, 2-stage pipeline (80KB smem
// -> 2 CTAs/SM; cross-CTA overlap hides L2 latency — R10 proven config).
// ---------------------------------------------------------------------------
#define PADK   40
#define TILE_B (128 * PADK * 2)
#define STAGE3_B (4 * TILE_B)       // 40960
#define QKV_SMEM (2 * STAGE3_B)     // 81920

__global__ void __launch_bounds__(256) gemm_qkv(
    const __half* __restrict__ Ah, const __half* __restrict__ Al,
    const __half* __restrict__ wqh, const __half* __restrict__ wql,
    const __half* __restrict__ wkh, const __half* __restrict__ wkl,
    const __half* __restrict__ wvh, const __half* __restrict__ wvl,
    float* __restrict__ qout, float* __restrict__ kout, float* __restrict__ vout)
{
    extern __shared__ char smem[];
    const uint32_t sbase = smem_u32(smem);
    const int K = HH;

    const int tid  = threadIdx.x;
    const int wid  = tid >> 5, lane = tid & 31;
    const int wm   = wid >> 2;
    const int wn   = wid & 3;
    const int m0   = blockIdx.y * 128;
    const int n0g  = blockIdx.x * 128;

    const __half *Bh, *Bl;
    float* C;
    int n0, NN;
    if (n0g < QCOLS)              { Bh = wqh; Bl = wql; C = qout; n0 = n0g;          NN = QCOLS; }
    else if (n0g < QCOLS+KVCOLS)  { Bh = wkh; Bl = wkl; C = kout; n0 = n0g - QCOLS;  NN = KVCOLS; }
    else                          { Bh = wvh; Bl = wvl; C = vout; n0 = n0g - 3072;   NN = KVCOLS; }

    const __half* gb[4] = {
        Ah + (size_t)m0 * K, Al + (size_t)m0 * K,
        Bh + (size_t)n0 * K, Bl + (size_t)n0 * K };

    const int NC = K >> 5;

#define ISSUE3(c, s) do {                                                     \
    _Pragma("unroll")                                                         \
    for (int i = 0; i < 8; i++) {                                             \
        int e    = tid + i * 256;                                             \
        int t    = e >> 9;                                                    \
        int rem  = e & 511;                                                   \
        int row  = rem >> 2;                                                  \
        int c16  = rem & 3;                                                   \
        uint32_t sa = sbase + (s) * STAGE3_B + t * TILE_B + row * (PADK*2) + c16 * 16; \
        cp_async16(sa, gb[t] + (size_t)row * K + (c) * 32 + c16 * 8);         \
    }                                                                         \
    asm volatile("cp.async.commit_group;" ::: "memory");                      \
} while (0)

    float acc[4][4][4];
#pragma unroll
    for (int i = 0; i < 4; i++)
#pragma unroll
        for (int j = 0; j < 4; j++)
#pragma unroll
            for (int r = 0; r < 4; r++) acc[i][j][r] = 0.f;

    const uint32_t a_off = (uint32_t)((lane & 15) * (PADK*2) + (lane >> 4) * 16);
    const uint32_t b_off = (uint32_t)(((lane & 7) + ((lane >> 4) << 3)) * (PADK*2)
                                      + ((lane >> 3) & 1) * 16);

    ISSUE3(0, 0);

    for (int c = 0; c < NC; c++) {
        const int s = c & 1;
        if (c + 1 < NC) {
            ISSUE3(c + 1, (c + 1) & 1);
            asm volatile("cp.async.wait_group 1;" ::: "memory");
        } else {
            asm volatile("cp.async.wait_group 0;" ::: "memory");
        }
        __syncthreads();

        const uint32_t sAh = sbase + s * STAGE3_B;
        const uint32_t sAl = sAh + TILE_B;
        const uint32_t sBh = sAh + 2 * TILE_B;
        const uint32_t sBl = sAh + 3 * TILE_B;

#pragma unroll
        for (int ks = 0; ks < 2; ks++) {
            const uint32_t kbyte = (uint32_t)(ks * 32);

            uint32_t ah[4][4], al[4][4];
#pragma unroll
            for (int i = 0; i < 4; i++) {
                const uint32_t ro = (uint32_t)((wm * 64 + i * 16) * (PADK*2)) + kbyte;
                ldmatrix_x4(ah[i], sAh + ro + a_off);
                ldmatrix_x4(al[i], sAl + ro + a_off);
            }
            uint32_t bh[2][4], bl[2][4];
#pragma unroll
            for (int p = 0; p < 2; p++) {
                const uint32_t ro = (uint32_t)((wn * 32 + p * 16) * (PADK*2)) + kbyte;
                ldmatrix_x4(bh[p], sBh + ro + b_off);
                ldmatrix_x4(bl[p], sBl + ro + b_off);
            }
#pragma unroll
            for (int i = 0; i < 4; i++)
#pragma unroll
                for (int j = 0; j < 4; j++) {
                    const int p = j >> 1, u = (j & 1) * 2;
                    mma_f16(acc[i][j], ah[i], bh[p][u], bh[p][u+1]);
                    mma_f16(acc[i][j], ah[i], bl[p][u], bl[p][u+1]);
                    mma_f16(acc[i][j], al[i], bh[p][u], bh[p][u+1]);
                }
        }
        __syncthreads();
    }
#undef ISSUE3

    const int rbase = m0 + wm * 64 + (lane >> 2);
    const int cbase = n0 + wn * 32 + (lane & 3) * 2;
#pragma unroll
    for (int i = 0; i < 4; i++)
#pragma unroll
        for (int j = 0; j < 4; j++) {
            float* p0 = C + (size_t)(rbase + i * 16) * NN + cbase + j * 8;
            float* p1 = p0 + 8 * (size_t)NN;
            *(float2*)p0 = make_float2(acc[i][j][0], acc[i][j][1]);
            *(float2*)p1 = make_float2(acc[i][j][2], acc[i][j][3]);
        }
}

// ---------------------------------------------------------------------------
// Output projection, 1-PASS fp16 HMMA (out = ao_h * Wo_h^T), 2-stage pipeline
// (40KB smem -> high occupancy). Wo_l dropped: ~2.4e-4 term, inside budget.
// ---------------------------------------------------------------------------
#define STAGE1_B (2 * TILE_B)       // 20480
#define WO_SMEM (2 * STAGE1_B)      // 40960

__global__ void __launch_bounds__(256) gemm_wo(
    const __half* __restrict__ Ah,
    const __half* __restrict__ Bh,
    float* __restrict__ C)
{
    extern __shared__ char smem[];
    const uint32_t sbase = smem_u32(smem);
    const int K = QCOLS, NN = HH;

    const int tid  = threadIdx.x;
    const int wid  = tid >> 5, lane = tid & 31;
    const int wm   = wid >> 2;
    const int wn   = wid & 3;
    const int m0   = blockIdx.y * 128, n0 = blockIdx.x * 128;

    const __half* gb[2] = { Ah + (size_t)m0 * K, Bh + (size_t)n0 * K };

    const int NC = K >> 5;   // 64

#define ISSUE1(c, s) do {                                                     \
    _Pragma("unroll")                                                         \
    for (int i = 0; i < 4; i++) {                                             \
        int e    = tid + i * 256;                                             \
        int t    = e >> 9;                                                    \
        int rem  = e & 511;                                                   \
        int row  = rem >> 2;                                                  \
        int c16  = rem & 3;                                                   \
        uint32_t sa = sbase + (s) * STAGE1_B + t * TILE_B + row * (PADK*2) + c16 * 16; \
        cp_async16(sa, gb[t] + (size_t)row * K + (c) * 32 + c16 * 8);         \
    }                                                                         \
    asm volatile("cp.async.commit_group;" ::: "memory");                      \
} while (0)

    float acc[4][4][4];
#pragma unroll
    for (int i = 0; i < 4; i++)
#pragma unroll
        for (int j = 0; j < 4; j++)
#pragma unroll
            for (int r = 0; r < 4; r++) acc[i][j][r] = 0.f;

    const uint32_t a_off = (uint32_t)((lane & 15) * (PADK*2) + (lane >> 4) * 16);
    const uint32_t b_off = (uint32_t)(((lane & 7) + ((lane >> 4) << 3)) * (PADK*2)
                                      + ((lane >> 3) & 1) * 16);

    ISSUE1(0, 0);

    for (int c = 0; c < NC; c++) {
        const int s = c & 1;
        if (c + 1 < NC) {
            ISSUE1(c + 1, (c + 1) & 1);
            asm volatile("cp.async.wait_group 1;" ::: "memory");
        } else {
            asm volatile("cp.async.wait_group 0;" ::: "memory");
        }
        __syncthreads();

        const uint32_t sAh = sbase + s * STAGE1_B;
        const uint32_t sBh = sAh + TILE_B;

#pragma unroll
        for (int ks = 0; ks < 2; ks++) {
            const uint32_t kbyte = (uint32_t)(ks * 32);

            uint32_t ah[4][4];
#pragma unroll
            for (int i = 0; i < 4; i++) {
                const uint32_t ro = (uint32_t)((wm * 64 + i * 16) * (PADK*2)) + kbyte;
                ldmatrix_x4(ah[i], sAh + ro + a_off);
            }
            uint32_t bh[2][4];
#pragma unroll
            for (int p = 0; p < 2; p++) {
                const uint32_t ro = (uint32_t)((wn * 32 + p * 16) * (PADK*2)) + kbyte;
                ldmatrix_x4(bh[p], sBh + ro + b_off);
            }
#pragma unroll
            for (int i = 0; i < 4; i++)
#pragma unroll
                for (int j = 0; j < 4; j++) {
                    const int p = j >> 1, u = (j & 1) * 2;
                    mma_f16(acc[i][j], ah[i], bh[p][u], bh[p][u+1]);
                }
        }
        __syncthreads();
    }
#undef ISSUE1

    const int rbase = m0 + wm * 64 + (lane >> 2);
    const int cbase = n0 + wn * 32 + (lane & 3) * 2;
#pragma unroll
    for (int i = 0; i < 4; i++)
#pragma unroll
        for (int j = 0; j < 4; j++) {
            float* p0 = C + (size_t)(rbase + i * 16) * NN + cbase + j * 8;
            float* p1 = p0 + 8 * (size_t)NN;
            *(float2*)p0 = make_float2(acc[i][j][0], acc[i][j][1]);
            *(float2*)p1 = make_float2(acc[i][j][2], acc[i][j][3]);
        }
}

// ---------------------------------------------------------------------------
// RMSNorm (+ optional weight) + RoPE — warp-per-(row,head), float4 I/O,
// shuffle-only reduction. Also resets the attention work counter.
// ---------------------------------------------------------------------------
__global__ void __launch_bounds__(256) rmsrope_kernel(
    const float* __restrict__ cosb, const float* __restrict__ sinb,
    const float* __restrict__ qw,  const float* __restrict__ kw)
{
    if (blockIdx.x == 0 && threadIdx.x == 0) g_work_ctr = 0;

    const int gw   = blockIdx.x * 8 + (threadIdx.x >> 5);
    const int row  = gw >> 4;
    const int part = gw & 15;
    const int lane = threadIdx.x & 31;
    const int d0   = lane * 4;

    const float* ptr;
    __half *hp, *lp = nullptr;
    const float* w = nullptr;
    bool do_rope = true;
    if (part < 8) {
        size_t off = (size_t)row * QCOLS + part * DD;
        ptr = g_q + off; hp = g_qh + off; lp = g_ql + off; w = qw;
    } else if (part < 12) {
        size_t off = (size_t)row * KVCOLS + (part - 8) * DD;
        ptr = g_k + off; hp = g_kh + off; lp = g_kl + off; w = kw;
    } else {
        size_t off = (size_t)row * KVCOLS + (part - 12) * DD;
        ptr = g_v + off; hp = g_vh + off; do_rope = false;
    }

    float4 x1 = *(const float4*)(ptr + d0);
    float4 x2 = *(const float4*)(ptr + 128 + d0);
    float ss = x1.x*x1.x + x1.y*x1.y + x1.z*x1.z + x1.w*x1.w
             + x2.x*x2.x + x2.y*x2.y + x2.z*x2.z + x2.w*x2.w;
#pragma unroll
    for (int o = 16; o; o >>= 1) ss += __shfl_xor_sync(0xffffffffu, ss, o);
    const float inv = rsqrtf(ss * (1.0f / DD) + 1e-6f);

    float y1[4] = { x1.x*inv, x1.y*inv, x1.z*inv, x1.w*inv };
    float y2[4] = { x2.x*inv, x2.y*inv, x2.z*inv, x2.w*inv };

    if (w) {
        float4 w1 = *(const float4*)(w + d0);
        float4 w2 = *(const float4*)(w + 128 + d0);
        y1[0] *= 1.f + w1.x; y1[1] *= 1.f + w1.y;
        y1[2] *= 1.f + w1.z; y1[3] *= 1.f + w1.w;
        y2[0] *= 1.f + w2.x; y2[1] *= 1.f + w2.y;
        y2[2] *= 1.f + w2.z; y2[3] *= 1.f + w2.w;
    }

    float o1[4], o2[4];
    if (do_rope) {
        const int s = row & (SS - 1);
        const float* cb = cosb + (size_t)s * DD;
        const float* sb = sinb + (size_t)s * DD;
        float4 c1 = *(const float4*)(cb + d0);
        float4 s1 = *(const float4*)(sb + d0);
        float4 c2 = *(const float4*)(cb + 128 + d0);
        float4 s2 = *(const float4*)(sb + 128 + d0);
        o1[0] = y1[0]*c1.x - y2[0]*s1.x;  o1[1] = y1[1]*c1.y - y2[1]*s1.y;
        o1[2] = y1[2]*c1.z - y2[2]*s1.z;  o1[3] = y1[3]*c1.w - y2[3]*s1.w;
        o2[0] = y2[0]*c2.x + y1[0]*s2.x;  o2[1] = y2[1]*c2.y + y1[1]*s2.y;
        o2[2] = y2[2]*c2.z + y1[2]*s2.z;  o2[3] = y2[3]*c2.w + y1[3]*s2.w;
    } else {
#pragma unroll
        for (int i = 0; i < 4; i++) { o1[i] = y1[i]; o2[i] = y2[i]; }
    }

    uint2 h1, h2;
    h1.x = pack_h2(o1[0], o1[1]); h1.y = pack_h2(o1[2], o1[3]);
    h2.x = pack_h2(o2[0], o2[1]); h2.y = pack_h2(o2[2], o2[3]);
    *(uint2*)(hp + d0)       = h1;
    *(uint2*)(hp + 128 + d0) = h2;
    if (lp) {
        __half q10 = __float2half(o1[0]), q11 = __float2half(o1[1]);
        __half q12 = __float2half(o1[2]), q13 = __float2half(o1[3]);
        __half q20 = __float2half(o2[0]), q21 = __float2half(o2[1]);
        __half q22 = __float2half(o2[2]), q23 = __float2half(o2[3]);
        uint2 l1, l2;
        l1.x = pack_h2(o1[0] - __half2float(q10), o1[1] - __half2float(q11));
        l1.y = pack_h2(o1[2] - __half2float(q12), o1[3] - __half2float(q13));
        l2.x = pack_h2(o2[0] - __half2float(q20), o2[1] - __half2float(q21));
        l2.y = pack_h2(o2[2] - __half2float(q22), o2[3] - __half2float(q23));
        *(uint2*)(lp + d0)       = l1;
        *(uint2*)(lp + 128 + d0) = l2;
    }
}

// ---------------------------------------------------------------------------
// HMMA split-fp16 sliding-window flash attention — persistent work queue.
// QK^T: 3-pass. PV: single pass (Ph * Vh).
// ---------------------------------------------------------------------------
#define QSTR 528
#define QTILE (128 * QSTR)
#define KTILE (64 * QSTR)
#define ATT_SMEM (2*QTILE + 2*KTILE) // 202752
#define NWORK (16 * NHQ * BB)        // 256 work items

__global__ void __launch_bounds__(256, 1) attn_hmma()
{
    extern __shared__ char smem[];
    const uint32_t sb   = smem_u32(smem);
    const uint32_t qh_s = sb;
    const uint32_t ql_s = sb + QTILE;
    const uint32_t k0_s = sb + 2 * QTILE;    // slot0: K-hi
    const uint32_t k1_s = k0_s + KTILE;      // slot1: K-lo, then V

    const int tid  = threadIdx.x;
    const int wid  = tid >> 5, lane = tid & 31;
    const int wrow = wid * 16;

    __shared__ int s_item;

    const uint32_t a_off = (uint32_t)((wrow + (lane & 15)) * QSTR + (lane >> 4) * 16);
    const uint32_t b_off = (uint32_t)(((lane & 7) + ((lane >> 4) << 3)) * QSTR
                                      + ((lane >> 3) & 1) * 16);
    const uint32_t v_off = (uint32_t)((lane & 15) * QSTR + (lane >> 4) * 16);
    const int lg = lane >> 2;
    const int lc = (lane & 3) * 2;

    for (;;) {
        __syncthreads();
        if (tid == 0) s_item = atomicAdd(&g_work_ctr, 1);
        __syncthreads();
        const int item = s_item;
        if (item >= NWORK) break;

        const int rrr  = item >> 4;
        const int bh   = item & 15;
        const int qblk = 15 - rrr;
        const int h    = bh & 7;
        const int b    = bh >> 3;
        const int kvh  = h >> 1;
        const int qs   = qblk * 128;

        // ---- Q load (hi & lo) ----
        {
            const __half* qsrc[2] = {
                g_qh + (size_t)(b*SS + qs) * QCOLS + h * DD,
                g_ql + (size_t)(b*SS + qs) * QCOLS + h * DD };
#pragma unroll
            for (int i = 0; i < 32; i++) {
                int e = tid + i * 256;
                int arr = e >> 12;
                int rem = e & 4095;
                int row = rem >> 5, c16 = rem & 31;
                cp_async16((arr ? ql_s : qh_s) + row * QSTR + c16 * 16,
                           qsrc[arr] + (size_t)row * QCOLS + c16 * 8);
            }
            asm volatile("cp.async.commit_group;" ::: "memory");
        }

        float out[32][4];
#pragma unroll
        for (int nt = 0; nt < 32; nt++)
#pragma unroll
            for (int r = 0; r < 4; r++) out[nt][r] = 0.f;
        float mrow[2] = {-1e30f, -1e30f};
        float lrow[2] = {0.f, 0.f};

        const __half* khg = g_kh + (size_t)(b*SS) * KVCOLS + kvh * DD;
        const __half* klg = g_kl + (size_t)(b*SS) * KVCOLS + kvh * DD;
        const __half* vhg = g_vh + (size_t)(b*SS) * KVCOLS + kvh * DD;

        int ksmin = qs - (SWIN - 1);
        if (ksmin < 0) ksmin = 0;
        const int t0 = ksmin >> 6;
        const int t1 = (qs + 127) >> 6;

#define LOAD_TILE(dst, src, ks_) do {                                          \
    _Pragma("unroll")                                                          \
    for (int i = 0; i < 8; i++) {                                              \
        int e = tid + i * 256;                                                 \
        int row = e >> 5, c16 = e & 31;                                        \
        cp_async16((dst) + row * QSTR + c16 * 16,                              \
                   (src) + (size_t)((ks_) + row) * KVCOLS + c16 * 8);          \
    }                                                                          \
    asm volatile("cp.async.commit_group;" ::: "memory");                       \
} while (0)

        LOAD_TILE(k0_s, khg, t0 << 6);
        LOAD_TILE(k1_s, klg, t0 << 6);

        for (int kt = t0; kt <= t1; kt++) {
            const int ks = kt << 6;
            const bool more = (kt < t1);

            asm volatile("cp.async.wait_group 0;" ::: "memory");
            __syncthreads();

            // ---- S = Q K^T (3-pass, fp32 acc) ----
            float sacc[8][4];
#pragma unroll
            for (int j = 0; j < 8; j++)
#pragma unroll
                for (int r = 0; r < 4; r++) sacc[j][r] = 0.f;

#pragma unroll
            for (int ks16 = 0; ks16 < 16; ks16++) {
                uint32_t qf_h[4], qf_l[4];
                ldmatrix_x4(qf_h, qh_s + a_off + ks16 * 32);
                ldmatrix_x4(qf_l, ql_s + a_off + ks16 * 32);
#pragma unroll
                for (int jp = 0; jp < 4; jp++) {
                    uint32_t kf_h[4], kf_l[4];
                    const uint32_t ro = (uint32_t)(jp * 16 * QSTR) + ks16 * 32;
                    ldmatrix_x4(kf_h, k0_s + ro + b_off);
                    ldmatrix_x4(kf_l, k1_s + ro + b_off);
#pragma unroll
                    for (int u = 0; u < 2; u++) {
                        const int j = jp * 2 + u;
                        mma_f16(sacc[j], qf_h, kf_h[u*2], kf_h[u*2+1]);
                        mma_f16(sacc[j], qf_h, kf_l[u*2], kf_l[u*2+1]);
                        mma_f16(sacc[j], qf_l, kf_h[u*2], kf_h[u*2+1]);
                    }
                }
            }
            __syncthreads();

            LOAD_TILE(k1_s, vhg, ks);
            if (more) LOAD_TILE(k0_s, khg, ks + 64);

            // ---- mask + online softmax (warp-local) ----
            uint32_t ph[8][2];
#pragma unroll
            for (int g = 0; g < 2; g++) {
                const int qi = qs + wrow + lg + g * 8;
                float mloc = -1e30f;
#pragma unroll
                for (int j = 0; j < 8; j++)
#pragma unroll
                    for (int e = 0; e < 2; e++) {
                        const int kj = ks + j * 8 + lc + e;
                        float s = sacc[j][g*2+e];
                        if (kj > qi || kj <= qi - SWIN) s = -1e30f;
                        sacc[j][g*2+e] = s;
                        mloc = fmaxf(mloc, s);
                    }
                mloc = fmaxf(mloc, __shfl_xor_sync(0xffffffffu, mloc, 1));
                mloc = fmaxf(mloc, __shfl_xor_sync(0xffffffffu, mloc, 2));
                const float mnew = fmaxf(mrow[g], mloc);
                const float corr = __expf(mrow[g] - mnew);
                float ls = 0.f;
#pragma unroll
                for (int j = 0; j < 8; j++)
#pragma unroll
                    for (int e = 0; e < 2; e++) {
                        float s = sacc[j][g*2+e];
                        float p = (s <= -1e29f) ? 0.f : __expf(s - mnew);
                        sacc[j][g*2+e] = p;
                        ls += p;
                    }
                ls += __shfl_xor_sync(0xffffffffu, ls, 1);
                ls += __shfl_xor_sync(0xffffffffu, ls, 2);
                lrow[g] = lrow[g] * corr + ls;
                mrow[g] = mnew;
#pragma unroll
                for (int nt = 0; nt < 32; nt++) {
                    out[nt][g*2+0] *= corr;
                    out[nt][g*2+1] *= corr;
                }
            }
            // pack P -> fp16 A-fragments (hi only)
#pragma unroll
            for (int j = 0; j < 8; j++)
#pragma unroll
                for (int g = 0; g < 2; g++)
                    ph[j][g] = pack_h2(sacc[j][g*2+0], sacc[j][g*2+1]);

            if (more) { asm volatile("cp.async.wait_group 1;" ::: "memory"); }
            else      { asm volatile("cp.async.wait_group 0;" ::: "memory"); }
            __syncthreads();

            // ---- O += P V (single pass; V in slot1) ----
#pragma unroll
            for (int s = 0; s < 4; s++) {
                uint32_t aph[4] = { ph[2*s][0], ph[2*s][1], ph[2*s+1][0], ph[2*s+1][1] };
                const uint32_t krow = (uint32_t)(s * 16 * QSTR);
#pragma unroll
                for (int np = 0; np < 16; np++) {
                    uint32_t vf_h[4];
                    const uint32_t vo = krow + (uint32_t)(np * 32) + v_off;
                    ldmatrix_x4_t(vf_h, k1_s + vo);
#pragma unroll
                    for (int u = 0; u < 2; u++) {
                        const int nt = np * 2 + u;
                        mma_f16(out[nt], aph, vf_h[u*2], vf_h[u*2+1]);
                    }
                }
            }
            __syncthreads();

            if (more) LOAD_TILE(k1_s, klg, ks + 64);
        }
#undef LOAD_TILE

        // ---- epilogue ----
#pragma unroll
        for (int g = 0; g < 2; g++) {
            const float inv = 1.0f / lrow[g];
            const int row = qs + wrow + lg + g * 8;
            __half* oh = g_ao_h + (size_t)(b*SS + row) * QCOLS + h * DD + lc;
#pragma unroll
            for (int nt = 0; nt < 32; nt++) {
                *(uint32_t*)(oh + nt*8) = pack_h2(out[nt][g*2+0] * inv,
                                                  out[nt][g*2+1] * inv);
            }
        }
    }
}

// ---------------------------------------------------------------------------
extern "C" void kernel_launch(void* const* d_in, const int* in_sizes, int n_in,
                              void* d_out, int out_size)
{
    (void)in_sizes; (void)n_in; (void)out_size;
    const float* hidden = (const float*)d_in[0];
    // d_in[1] = attention_mask — analytic, unused
    const float* cosb = (const float*)d_in[2];
    const float* sinb = (const float*)d_in[3];
    const float* Wq = (const float*)d_in[4];
    const float* Wk = (const float*)d_in[5];
    const float* Wv = (const float*)d_in[6];
    const float* Wo = (const float*)d_in[7];
    const float* qw = (const float*)d_in[8];
    const float* kw = (const float*)d_in[9];
    float* out = (float*)d_out;

    float *qp, *kp, *vp;
    cudaGetSymbolAddress((void**)&qp, g_q);
    cudaGetSymbolAddress((void**)&kp, g_k);
    cudaGetSymbolAddress((void**)&vp, g_v);
    __half *hid_h, *hid_l, *wq_h, *wq_l, *wk_h, *wk_l, *wv_h, *wv_l,
           *wo_h, *wo_l, *ao_h;
    cudaGetSymbolAddress((void**)&hid_h, g_hid_h);
    cudaGetSymbolAddress((void**)&hid_l, g_hid_l);
    cudaGetSymbolAddress((void**)&wq_h,  g_wq_h);
    cudaGetSymbolAddress((void**)&wq_l,  g_wq_l);
    cudaGetSymbolAddress((void**)&wk_h,  g_wk_h);
    cudaGetSymbolAddress((void**)&wk_l,  g_wk_l);
    cudaGetSymbolAddress((void**)&wv_h,  g_wv_h);
    cudaGetSymbolAddress((void**)&wv_l,  g_wv_l);
    cudaGetSymbolAddress((void**)&wo_h,  g_wo_h);
    cudaGetSymbolAddress((void**)&wo_l,  g_wo_l);
    cudaGetSymbolAddress((void**)&ao_h,  g_ao_h);

    cudaFuncSetAttribute(gemm_qkv, cudaFuncAttributeMaxDynamicSharedMemorySize, QKV_SMEM);
    cudaFuncSetAttribute(gemm_wo,  cudaFuncAttributeMaxDynamicSharedMemorySize, WO_SMEM);
    cudaFuncSetAttribute(attn_hmma, cudaFuncAttributeMaxDynamicSharedMemorySize, ATT_SMEM);

    // 0) split fp32 -> fp16 hi/lo
    {
        int n4;
        n4 = (int)((size_t)MROWS * HH / 4);
        split_kernel<<<(n4 + 255) / 256, 256>>>(hidden, hid_h, hid_l, n4);
        n4 = (int)((size_t)QCOLS * HH / 4);
        split_kernel<<<(n4 + 255) / 256, 256>>>(Wq, wq_h, wq_l, n4);
        n4 = (int)((size_t)KVCOLS * HH / 4);
        split_kernel<<<(n4 + 255) / 256, 256>>>(Wk, wk_h, wk_l, n4);
        split_kernel<<<(n4 + 255) / 256, 256>>>(Wv, wv_h, wv_l, n4);
        n4 = (int)((size_t)HH * QCOLS / 4);
        split_kernel<<<(n4 + 255) / 256, 256>>>(Wo, wo_h, wo_l, n4);
    }

    // 1) fused QKV projection (3-pass, 2-stage, occ-2)
    gemm_qkv<<<dim3(32, 32), 256, QKV_SMEM>>>(
        hid_h, hid_l, wq_h, wq_l, wk_h, wk_l, wv_h, wv_l, qp, kp, vp);

    // 2) RMSNorm + RoPE (warp-per-row) -> fp16 hi/lo; resets work counter
    rmsrope_kernel<<<MROWS * 16 / 8, 256>>>(cosb, sinb, qw, kw);

    // 3) persistent HMMA sliding-window flash attention -> fp16 ao
    attn_hmma<<<152, 256, ATT_SMEM>>>();

    // 4) output projection (1-pass, 2-stage) -> fp32 d_out
    gemm_wo<<<dim3(HH/128, MROWS/128), 256, WO_SMEM>>>(ao_h, wo_h, out);
}

// round 13
// speedup vs baseline: 1.1838x; 1.0047x over previous
#include <cuda_runtime.h>
#include <cuda_fp16.h>
#include <cstdint>
#include <math.h>

// Problem constants
#define BB    2
#define SS    2048
#define HH    2560
#define NHQ   8
#define NKV   4
#define DD    256
#define SWIN  1024
#define MROWS (BB*SS)          // 4096
#define QCOLS (NHQ*DD)         // 2048
#define KVCOLS (NKV*DD)        // 1024

// ---------------- scratch (allocation-free rule: device globals) ------------
__device__ float g_q [ (size_t)MROWS * QCOLS ];
__device__ float g_k [ (size_t)MROWS * KVCOLS ];
__device__ float g_v [ (size_t)MROWS * KVCOLS ];
__device__ int   g_work_ctr;

// split-fp16 operands
__device__ __half g_hid_h[(size_t)MROWS*HH],  g_hid_l[(size_t)MROWS*HH];
__device__ __half g_wq_h [(size_t)QCOLS*HH],  g_wq_l [(size_t)QCOLS*HH];
__device__ __half g_wk_h [(size_t)KVCOLS*HH], g_wk_l [(size_t)KVCOLS*HH];
__device__ __half g_wv_h [(size_t)KVCOLS*HH], g_wv_l [(size_t)KVCOLS*HH];
__device__ __half g_wo_h [(size_t)HH*QCOLS],  g_wo_l [(size_t)HH*QCOLS];
// post-rmsnorm/rope q/k (hi/lo) and v (hi only)
__device__ __half g_qh[(size_t)MROWS*QCOLS],  g_ql[(size_t)MROWS*QCOLS];
__device__ __half g_kh[(size_t)MROWS*KVCOLS], g_kl[(size_t)MROWS*KVCOLS];
__device__ __half g_vh[(size_t)MROWS*KVCOLS];
// attention output (hi only)
__device__ __half g_ao_h[(size_t)MROWS*QCOLS];

// ---------------- helpers ----------------------------------------------------
__device__ __forceinline__ uint32_t smem_u32(const void* p) {
    uint32_t a;
    asm("{ .reg .u64 t; cvta.to.shared.u64 t, %1; cvt.u32.u64 %0, t; }"
        : "=r"(a) : "l"(p));
    return a;
}
__device__ __forceinline__ void ldmatrix_x4(uint32_t* r, uint32_t addr) {
    asm volatile("ldmatrix.sync.aligned.m8n8.x4.shared.b16 {%0,%1,%2,%3}, [%4];"
                 : "=r"(r[0]), "=r"(r[1]), "=r"(r[2]), "=r"(r[3]) : "r"(addr));
}
__device__ __forceinline__ void ldmatrix_x4_t(uint32_t* r, uint32_t addr) {
    asm volatile("ldmatrix.sync.aligned.m8n8.x4.trans.shared.b16 {%0,%1,%2,%3}, [%4];"
                 : "=r"(r[0]), "=r"(r[1]), "=r"(r[2]), "=r"(r[3]) : "r"(addr));
}
__device__ __forceinline__ void mma_f16(float* d, const uint32_t* a,
                                        uint32_t b0, uint32_t b1) {
    asm volatile(
        "mma.sync.aligned.m16n8k16.row.col.f32.f16.f16.f32 "
        "{%0,%1,%2,%3}, {%4,%5,%6,%7}, {%8,%9}, {%0,%1,%2,%3};"
        : "+f"(d[0]), "+f"(d[1]), "+f"(d[2]), "+f"(d[3])
        : "r"(a[0]), "r"(a[1]), "r"(a[2]), "r"(a[3]), "r"(b0), "r"(b1));
}
__device__ __forceinline__ void cp_async16(uint32_t saddr, const void* gaddr) {
    asm volatile("cp.async.cg.shared.global [%0], [%1], 16;"
                 :: "r"(saddr), "l"(gaddr));
}
__device__ __forceinline__ uint32_t pack_h2(float a, float b) {
    __half2 t; t.x = __float2half(a); t.y = __float2half(b);
    return *(uint32_t*)&t;
}

// ---------------------------------------------------------------------------
// Merged split kernel: all 5 fp32 -> (hi, lo) fp16 conversions in ONE launch.
// Segment sizes (in float4 units) are multiples of 256 -> block-level dispatch.
//   hidden: 2621440 f4 -> blocks [0, 10240)
//   Wq    : 1310720 f4 -> blocks [10240, 15360)
//   Wk    :  655360 f4 -> blocks [15360, 17920)
//   Wv    :  655360 f4 -> blocks [17920, 20480)
//   Wo    : 1310720 f4 -> blocks [20480, 25600)
// ---------------------------------------------------------------------------
#define SPLIT_BLOCKS 25600

__global__ void __launch_bounds__(256) split_all(
    const float* __restrict__ hid, const float* __restrict__ wq,
    const float* __restrict__ wk,  const float* __restrict__ wv,
    const float* __restrict__ wo,
    __half* __restrict__ hid_h, __half* __restrict__ hid_l,
    __half* __restrict__ wq_h,  __half* __restrict__ wq_l,
    __half* __restrict__ wk_h,  __half* __restrict__ wk_l,
    __half* __restrict__ wv_h,  __half* __restrict__ wv_l,
    __half* __restrict__ wo_h,  __half* __restrict__ wo_l)
{
    const int b = blockIdx.x;
    const float* src;
    __half *hi, *lo;
    int i;
    if (b < 10240)      { src = hid; hi = hid_h; lo = hid_l; i = b * 256 + threadIdx.x; }
    else if (b < 15360) { src = wq;  hi = wq_h;  lo = wq_l;  i = (b - 10240) * 256 + threadIdx.x; }
    else if (b < 17920) { src = wk;  hi = wk_h;  lo = wk_l;  i = (b - 15360) * 256 + threadIdx.x; }
    else if (b < 20480) { src = wv;  hi = wv_h;  lo = wv_l;  i = (b - 17920) * 256 + threadIdx.x; }
    else                { src = wo;  hi = wo_h;  lo = wo_l;  i = (b - 20480) * 256 + threadIdx.x; }

    float4 v = ((const float4*)src)[i];
    __half hx = __float2half(v.x), hy = __float2half(v.y);
    __half hz = __float2half(v.z), hw = __float2half(v.w);
    __half lx = __float2half(v.x - __half2float(hx));
    __half ly = __float2half(v.y - __half2float(hy));
    __half lz = __float2half(v.z - __half2float(hz));
    __half lw = __float2half(v.w - __half2float(hw));
    __half2 h01; h01.x = hx; h01.y = hy;
    __half2 h23; h23.x = hz; h23.y = hw;
    __half2 l01; l01.x = lx; l01.y = ly;
    __half2 l23; l23.x = lz; l23.y = lw;
    ((__half2*)hi)[2*i]   = h01;
    ((__half2*)hi)[2*i+1] = h23;
    ((__half2*)lo)[2*i]   = l01;
    ((__half2*)lo)[2*i+1] = l23;
}

// ---------------------------------------------------------------------------
// Fused QKV projection, 3-pass split-fp16 HMMA, 2-stage pipeline (80KB smem
// -> 2 CTAs/SM; cross-CTA overlap hides L2 latency).
// ---------------------------------------------------------------------------
#define PADK   40
#define TILE_B (128 * PADK * 2)
#define STAGE3_B (4 * TILE_B)       // 40960
#define QKV_SMEM (2 * STAGE3_B)     // 81920

__global__ void __launch_bounds__(256) gemm_qkv(
    const __half* __restrict__ Ah, const __half* __restrict__ Al,
    const __half* __restrict__ wqh, const __half* __restrict__ wql,
    const __half* __restrict__ wkh, const __half* __restrict__ wkl,
    const __half* __restrict__ wvh, const __half* __restrict__ wvl,
    float* __restrict__ qout, float* __restrict__ kout, float* __restrict__ vout)
{
    extern __shared__ char smem[];
    const uint32_t sbase = smem_u32(smem);
    const int K = HH;

    const int tid  = threadIdx.x;
    const int wid  = tid >> 5, lane = tid & 31;
    const int wm   = wid >> 2;
    const int wn   = wid & 3;
    const int m0   = blockIdx.y * 128;
    const int n0g  = blockIdx.x * 128;

    const __half *Bh, *Bl;
    float* C;
    int n0, NN;
    if (n0g < QCOLS)              { Bh = wqh; Bl = wql; C = qout; n0 = n0g;          NN = QCOLS; }
    else if (n0g < QCOLS+KVCOLS)  { Bh = wkh; Bl = wkl; C = kout; n0 = n0g - QCOLS;  NN = KVCOLS; }
    else                          { Bh = wvh; Bl = wvl; C = vout; n0 = n0g - 3072;   NN = KVCOLS; }

    const __half* gb[4] = {
        Ah + (size_t)m0 * K, Al + (size_t)m0 * K,
        Bh + (size_t)n0 * K, Bl + (size_t)n0 * K };

    const int NC = K >> 5;

#define ISSUE3(c, s) do {                                                     \
    _Pragma("unroll")                                                         \
    for (int i = 0; i < 8; i++) {                                             \
        int e    = tid + i * 256;                                             \
        int t    = e >> 9;                                                    \
        int rem  = e & 511;                                                   \
        int row  = rem >> 2;                                                  \
        int c16  = rem & 3;                                                   \
        uint32_t sa = sbase + (s) * STAGE3_B + t * TILE_B + row * (PADK*2) + c16 * 16; \
        cp_async16(sa, gb[t] + (size_t)row * K + (c) * 32 + c16 * 8);         \
    }                                                                         \
    asm volatile("cp.async.commit_group;" ::: "memory");                      \
} while (0)

    float acc[4][4][4];
#pragma unroll
    for (int i = 0; i < 4; i++)
#pragma unroll
        for (int j = 0; j < 4; j++)
#pragma unroll
            for (int r = 0; r < 4; r++) acc[i][j][r] = 0.f;

    const uint32_t a_off = (uint32_t)((lane & 15) * (PADK*2) + (lane >> 4) * 16);
    const uint32_t b_off = (uint32_t)(((lane & 7) + ((lane >> 4) << 3)) * (PADK*2)
                                      + ((lane >> 3) & 1) * 16);

    ISSUE3(0, 0);

    for (int c = 0; c < NC; c++) {
        const int s = c & 1;
        if (c + 1 < NC) {
            ISSUE3(c + 1, (c + 1) & 1);
            asm volatile("cp.async.wait_group 1;" ::: "memory");
        } else {
            asm volatile("cp.async.wait_group 0;" ::: "memory");
        }
        __syncthreads();

        const uint32_t sAh = sbase + s * STAGE3_B;
        const uint32_t sAl = sAh + TILE_B;
        const uint32_t sBh = sAh + 2 * TILE_B;
        const uint32_t sBl = sAh + 3 * TILE_B;

#pragma unroll
        for (int ks = 0; ks < 2; ks++) {
            const uint32_t kbyte = (uint32_t)(ks * 32);

            uint32_t ah[4][4], al[4][4];
#pragma unroll
            for (int i = 0; i < 4; i++) {
                const uint32_t ro = (uint32_t)((wm * 64 + i * 16) * (PADK*2)) + kbyte;
                ldmatrix_x4(ah[i], sAh + ro + a_off);
                ldmatrix_x4(al[i], sAl + ro + a_off);
            }
            uint32_t bh[2][4], bl[2][4];
#pragma unroll
            for (int p = 0; p < 2; p++) {
                const uint32_t ro = (uint32_t)((wn * 32 + p * 16) * (PADK*2)) + kbyte;
                ldmatrix_x4(bh[p], sBh + ro + b_off);
                ldmatrix_x4(bl[p], sBl + ro + b_off);
            }
#pragma unroll
            for (int i = 0; i < 4; i++)
#pragma unroll
                for (int j = 0; j < 4; j++) {
                    const int p = j >> 1, u = (j & 1) * 2;
                    mma_f16(acc[i][j], ah[i], bh[p][u], bh[p][u+1]);
                    mma_f16(acc[i][j], ah[i], bl[p][u], bl[p][u+1]);
                    mma_f16(acc[i][j], al[i], bh[p][u], bh[p][u+1]);
                }
        }
        __syncthreads();
    }
#undef ISSUE3

    const int rbase = m0 + wm * 64 + (lane >> 2);
    const int cbase = n0 + wn * 32 + (lane & 3) * 2;
#pragma unroll
    for (int i = 0; i < 4; i++)
#pragma unroll
        for (int j = 0; j < 4; j++) {
            float* p0 = C + (size_t)(rbase + i * 16) * NN + cbase + j * 8;
            float* p1 = p0 + 8 * (size_t)NN;
            *(float2*)p0 = make_float2(acc[i][j][0], acc[i][j][1]);
            *(float2*)p1 = make_float2(acc[i][j][2], acc[i][j][3]);
        }
}

// ---------------------------------------------------------------------------
// Output projection, 1-PASS fp16 HMMA (out = ao_h * Wo_h^T), 2-stage pipeline.
// ---------------------------------------------------------------------------
#define STAGE1_B (2 * TILE_B)       // 20480
#define WO_SMEM (2 * STAGE1_B)      // 40960

__global__ void __launch_bounds__(256) gemm_wo(
    const __half* __restrict__ Ah,
    const __half* __restrict__ Bh,
    float* __restrict__ C)
{
    extern __shared__ char smem[];
    const uint32_t sbase = smem_u32(smem);
    const int K = QCOLS, NN = HH;

    const int tid  = threadIdx.x;
    const int wid  = tid >> 5, lane = tid & 31;
    const int wm   = wid >> 2;
    const int wn   = wid & 3;
    const int m0   = blockIdx.y * 128, n0 = blockIdx.x * 128;

    const __half* gb[2] = { Ah + (size_t)m0 * K, Bh + (size_t)n0 * K };

    const int NC = K >> 5;   // 64

#define ISSUE1(c, s) do {                                                     \
    _Pragma("unroll")                                                         \
    for (int i = 0; i < 4; i++) {                                             \
        int e    = tid + i * 256;                                             \
        int t    = e >> 9;                                                    \
        int rem  = e & 511;                                                   \
        int row  = rem >> 2;                                                  \
        int c16  = rem & 3;                                                   \
        uint32_t sa = sbase + (s) * STAGE1_B + t * TILE_B + row * (PADK*2) + c16 * 16; \
        cp_async16(sa, gb[t] + (size_t)row * K + (c) * 32 + c16 * 8);         \
    }                                                                         \
    asm volatile("cp.async.commit_group;" ::: "memory");                      \
} while (0)

    float acc[4][4][4];
#pragma unroll
    for (int i = 0; i < 4; i++)
#pragma unroll
        for (int j = 0; j < 4; j++)
#pragma unroll
            for (int r = 0; r < 4; r++) acc[i][j][r] = 0.f;

    const uint32_t a_off = (uint32_t)((lane & 15) * (PADK*2) + (lane >> 4) * 16);
    const uint32_t b_off = (uint32_t)(((lane & 7) + ((lane >> 4) << 3)) * (PADK*2)
                                      + ((lane >> 3) & 1) * 16);

    ISSUE1(0, 0);

    for (int c = 0; c < NC; c++) {
        const int s = c & 1;
        if (c + 1 < NC) {
            ISSUE1(c + 1, (c + 1) & 1);
            asm volatile("cp.async.wait_group 1;" ::: "memory");
        } else {
            asm volatile("cp.async.wait_group 0;" ::: "memory");
        }
        __syncthreads();

        const uint32_t sAh = sbase + s * STAGE1_B;
        const uint32_t sBh = sAh + TILE_B;

#pragma unroll
        for (int ks = 0; ks < 2; ks++) {
            const uint32_t kbyte = (uint32_t)(ks * 32);

            uint32_t ah[4][4];
#pragma unroll
            for (int i = 0; i < 4; i++) {
                const uint32_t ro = (uint32_t)((wm * 64 + i * 16) * (PADK*2)) + kbyte;
                ldmatrix_x4(ah[i], sAh + ro + a_off);
            }
            uint32_t bh[2][4];
#pragma unroll
            for (int p = 0; p < 2; p++) {
                const uint32_t ro = (uint32_t)((wn * 32 + p * 16) * (PADK*2)) + kbyte;
                ldmatrix_x4(bh[p], sBh + ro + b_off);
            }
#pragma unroll
            for (int i = 0; i < 4; i++)
#pragma unroll
                for (int j = 0; j < 4; j++) {
                    const int p = j >> 1, u = (j & 1) * 2;
                    mma_f16(acc[i][j], ah[i], bh[p][u], bh[p][u+1]);
                }
        }
        __syncthreads();
    }
#undef ISSUE1

    const int rbase = m0 + wm * 64 + (lane >> 2);
    const int cbase = n0 + wn * 32 + (lane & 3) * 2;
#pragma unroll
    for (int i = 0; i < 4; i++)
#pragma unroll
        for (int j = 0; j < 4; j++) {
            float* p0 = C + (size_t)(rbase + i * 16) * NN + cbase + j * 8;
            float* p1 = p0 + 8 * (size_t)NN;
            *(float2*)p0 = make_float2(acc[i][j][0], acc[i][j][1]);
            *(float2*)p1 = make_float2(acc[i][j][2], acc[i][j][3]);
        }
}

// ---------------------------------------------------------------------------
// RMSNorm (+ optional weight) + RoPE — warp-per-(row,head), float4 I/O,
// shuffle-only reduction. Also resets the attention work counter.
// ---------------------------------------------------------------------------
__global__ void __launch_bounds__(256) rmsrope_kernel(
    const float* __restrict__ cosb, const float* __restrict__ sinb,
    const float* __restrict__ qw,  const float* __restrict__ kw)
{
    if (blockIdx.x == 0 && threadIdx.x == 0) g_work_ctr = 0;

    const int gw   = blockIdx.x * 8 + (threadIdx.x >> 5);
    const int row  = gw >> 4;
    const int part = gw & 15;
    const int lane = threadIdx.x & 31;
    const int d0   = lane * 4;

    const float* ptr;
    __half *hp, *lp = nullptr;
    const float* w = nullptr;
    bool do_rope = true;
    if (part < 8) {
        size_t off = (size_t)row * QCOLS + part * DD;
        ptr = g_q + off; hp = g_qh + off; lp = g_ql + off; w = qw;
    } else if (part < 12) {
        size_t off = (size_t)row * KVCOLS + (part - 8) * DD;
        ptr = g_k + off; hp = g_kh + off; lp = g_kl + off; w = kw;
    } else {
        size_t off = (size_t)row * KVCOLS + (part - 12) * DD;
        ptr = g_v + off; hp = g_vh + off; do_rope = false;
    }

    float4 x1 = *(const float4*)(ptr + d0);
    float4 x2 = *(const float4*)(ptr + 128 + d0);
    float ss = x1.x*x1.x + x1.y*x1.y + x1.z*x1.z + x1.w*x1.w
             + x2.x*x2.x + x2.y*x2.y + x2.z*x2.z + x2.w*x2.w;
#pragma unroll
    for (int o = 16; o; o >>= 1) ss += __shfl_xor_sync(0xffffffffu, ss, o);
    const float inv = rsqrtf(ss * (1.0f / DD) + 1e-6f);

    float y1[4] = { x1.x*inv, x1.y*inv, x1.z*inv, x1.w*inv };
    float y2[4] = { x2.x*inv, x2.y*inv, x2.z*inv, x2.w*inv };

    if (w) {
        float4 w1 = *(const float4*)(w + d0);
        float4 w2 = *(const float4*)(w + 128 + d0);
        y1[0] *= 1.f + w1.x; y1[1] *= 1.f + w1.y;
        y1[2] *= 1.f + w1.z; y1[3] *= 1.f + w1.w;
        y2[0] *= 1.f + w2.x; y2[1] *= 1.f + w2.y;
        y2[2] *= 1.f + w2.z; y2[3] *= 1.f + w2.w;
    }

    float o1[4], o2[4];
    if (do_rope) {
        const int s = row & (SS - 1);
        const float* cb = cosb + (size_t)s * DD;
        const float* sb = sinb + (size_t)s * DD;
        float4 c1 = *(const float4*)(cb + d0);
        float4 s1 = *(const float4*)(sb + d0);
        float4 c2 = *(const float4*)(cb + 128 + d0);
        float4 s2 = *(const float4*)(sb + 128 + d0);
        o1[0] = y1[0]*c1.x - y2[0]*s1.x;  o1[1] = y1[1]*c1.y - y2[1]*s1.y;
        o1[2] = y1[2]*c1.z - y2[2]*s1.z;  o1[3] = y1[3]*c1.w - y2[3]*s1.w;
        o2[0] = y2[0]*c2.x + y1[0]*s2.x;  o2[1] = y2[1]*c2.y + y1[1]*s2.y;
        o2[2] = y2[2]*c2.z + y1[2]*s2.z;  o2[3] = y2[3]*c2.w + y1[3]*s2.w;
    } else {
#pragma unroll
        for (int i = 0; i < 4; i++) { o1[i] = y1[i]; o2[i] = y2[i]; }
    }

    uint2 h1, h2;
    h1.x = pack_h2(o1[0], o1[1]); h1.y = pack_h2(o1[2], o1[3]);
    h2.x = pack_h2(o2[0], o2[1]); h2.y = pack_h2(o2[2], o2[3]);
    *(uint2*)(hp + d0)       = h1;
    *(uint2*)(hp + 128 + d0) = h2;
    if (lp) {
        __half q10 = __float2half(o1[0]), q11 = __float2half(o1[1]);
        __half q12 = __float2half(o1[2]), q13 = __float2half(o1[3]);
        __half q20 = __float2half(o2[0]), q21 = __float2half(o2[1]);
        __half q22 = __float2half(o2[2]), q23 = __float2half(o2[3]);
        uint2 l1, l2;
        l1.x = pack_h2(o1[0] - __half2float(q10), o1[1] - __half2float(q11));
        l1.y = pack_h2(o1[2] - __half2float(q12), o1[3] - __half2float(q13));
        l2.x = pack_h2(o2[0] - __half2float(q20), o2[1] - __half2float(q21));
        l2.y = pack_h2(o2[2] - __half2float(q22), o2[3] - __half2float(q23));
        *(uint2*)(lp + d0)       = l1;
        *(uint2*)(lp + 128 + d0) = l2;
    }
}

// ---------------------------------------------------------------------------
// HMMA split-fp16 sliding-window flash attention — persistent work queue.
// QK^T: 3-pass. PV: single pass. Per-warp full-mask tile skip (exact).
// ---------------------------------------------------------------------------
#define QSTR 528
#define QTILE (128 * QSTR)
#define KTILE (64 * QSTR)
#define ATT_SMEM (2*QTILE + 2*KTILE) // 202752
#define NWORK (16 * NHQ * BB)        // 256 work items

__global__ void __launch_bounds__(256, 1) attn_hmma()
{
    extern __shared__ char smem[];
    const uint32_t sb   = smem_u32(smem);
    const uint32_t qh_s = sb;
    const uint32_t ql_s = sb + QTILE;
    const uint32_t k0_s = sb + 2 * QTILE;    // slot0: K-hi
    const uint32_t k1_s = k0_s + KTILE;      // slot1: K-lo, then V

    const int tid  = threadIdx.x;
    const int wid  = tid >> 5, lane = tid & 31;
    const int wrow = wid * 16;

    __shared__ int s_item;

    const uint32_t a_off = (uint32_t)((wrow + (lane & 15)) * QSTR + (lane >> 4) * 16);
    const uint32_t b_off = (uint32_t)(((lane & 7) + ((lane >> 4) << 3)) * QSTR
                                      + ((lane >> 3) & 1) * 16);
    const uint32_t v_off = (uint32_t)((lane & 15) * QSTR + (lane >> 4) * 16);
    const int lg = lane >> 2;
    const int lc = (lane & 3) * 2;

    for (;;) {
        __syncthreads();
        if (tid == 0) s_item = atomicAdd(&g_work_ctr, 1);
        __syncthreads();
        const int item = s_item;
        if (item >= NWORK) break;

        const int rrr  = item >> 4;
        const int bh   = item & 15;
        const int qblk = 15 - rrr;
        const int h    = bh & 7;
        const int b    = bh >> 3;
        const int kvh  = h >> 1;
        const int qs   = qblk * 128;
        const int qlo  = qs + wrow;        // first q row owned by this warp

        // ---- Q load (hi & lo) ----
        {
            const __half* qsrc[2] = {
                g_qh + (size_t)(b*SS + qs) * QCOLS + h * DD,
                g_ql + (size_t)(b*SS + qs) * QCOLS + h * DD };
#pragma unroll
            for (int i = 0; i < 32; i++) {
                int e = tid + i * 256;
                int arr = e >> 12;
                int rem = e & 4095;
                int row = rem >> 5, c16 = rem & 31;
                cp_async16((arr ? ql_s : qh_s) + row * QSTR + c16 * 16,
                           qsrc[arr] + (size_t)row * QCOLS + c16 * 8);
            }
            asm volatile("cp.async.commit_group;" ::: "memory");
        }

        float out[32][4];
#pragma unroll
        for (int nt = 0; nt < 32; nt++)
#pragma unroll
            for (int r = 0; r < 4; r++) out[nt][r] = 0.f;
        float mrow[2] = {-1e30f, -1e30f};
        float lrow[2] = {0.f, 0.f};

        const __half* khg = g_kh + (size_t)(b*SS) * KVCOLS + kvh * DD;
        const __half* klg = g_kl + (size_t)(b*SS) * KVCOLS + kvh * DD;
        const __half* vhg = g_vh + (size_t)(b*SS) * KVCOLS + kvh * DD;

        int ksmin = qs - (SWIN - 1);
        if (ksmin < 0) ksmin = 0;
        const int t0 = ksmin >> 6;
        const int t1 = (qs + 127) >> 6;

#define LOAD_TILE(dst, src, ks_) do {                                          \
    _Pragma("unroll")                                                          \
    for (int i = 0; i < 8; i++) {                                              \
        int e = tid + i * 256;                                                 \
        int row = e >> 5, c16 = e & 31;                                        \
        cp_async16((dst) + row * QSTR + c16 * 16,                              \
                   (src) + (size_t)((ks_) + row) * KVCOLS + c16 * 8);          \
    }                                                                          \
    asm volatile("cp.async.commit_group;" ::: "memory");                       \
} while (0)

        LOAD_TILE(k0_s, khg, t0 << 6);
        LOAD_TILE(k1_s, klg, t0 << 6);

        for (int kt = t0; kt <= t1; kt++) {
            const int ks = kt << 6;
            const bool more = (kt < t1);
            // warp's 16 rows entirely masked for this K tile? (exact skip)
            const bool skipw = ((qlo + 15) < ks) || ((ks + 63) <= (qlo - SWIN));

            asm volatile("cp.async.wait_group 0;" ::: "memory");
            __syncthreads();

            // ---- S = Q K^T (3-pass, fp32 acc) ----
            float sacc[8][4];
            uint32_t ph[8][2];
            if (!skipw) {
#pragma unroll
                for (int j = 0; j < 8; j++)
#pragma unroll
                    for (int r = 0; r < 4; r++) sacc[j][r] = 0.f;

#pragma unroll
                for (int ks16 = 0; ks16 < 16; ks16++) {
                    uint32_t qf_h[4], qf_l[4];
                    ldmatrix_x4(qf_h, qh_s + a_off + ks16 * 32);
                    ldmatrix_x4(qf_l, ql_s + a_off + ks16 * 32);
#pragma unroll
                    for (int jp = 0; jp < 4; jp++) {
                        uint32_t kf_h[4], kf_l[4];
                        const uint32_t ro = (uint32_t)(jp * 16 * QSTR) + ks16 * 32;
                        ldmatrix_x4(kf_h, k0_s + ro + b_off);
                        ldmatrix_x4(kf_l, k1_s + ro + b_off);
#pragma unroll
                        for (int u = 0; u < 2; u++) {
                            const int j = jp * 2 + u;
                            mma_f16(sacc[j], qf_h, kf_h[u*2], kf_h[u*2+1]);
                            mma_f16(sacc[j], qf_h, kf_l[u*2], kf_l[u*2+1]);
                            mma_f16(sacc[j], qf_l, kf_h[u*2], kf_h[u*2+1]);
                        }
                    }
                }
            }
            __syncthreads();

            LOAD_TILE(k1_s, vhg, ks);
            if (more) LOAD_TILE(k0_s, khg, ks + 64);

            // ---- mask + online softmax (warp-local) ----
            if (!skipw) {
#pragma unroll
                for (int g = 0; g < 2; g++) {
                    const int qi = qs + wrow + lg + g * 8;
                    float mloc = -1e30f;
#pragma unroll
                    for (int j = 0; j < 8; j++)
#pragma unroll
                        for (int e = 0; e < 2; e++) {
                            const int kj = ks + j * 8 + lc + e;
                            float s = sacc[j][g*2+e];
                            if (kj > qi || kj <= qi - SWIN) s = -1e30f;
                            sacc[j][g*2+e] = s;
                            mloc = fmaxf(mloc, s);
                        }
                    mloc = fmaxf(mloc, __shfl_xor_sync(0xffffffffu, mloc, 1));
                    mloc = fmaxf(mloc, __shfl_xor_sync(0xffffffffu, mloc, 2));
                    const float mnew = fmaxf(mrow[g], mloc);
                    const float corr = __expf(mrow[g] - mnew);
                    float ls = 0.f;
#pragma unroll
                    for (int j = 0; j < 8; j++)
#pragma unroll
                        for (int e = 0; e < 2; e++) {
                            float s = sacc[j][g*2+e];
                            float p = (s <= -1e29f) ? 0.f : __expf(s - mnew);
                            sacc[j][g*2+e] = p;
                            ls += p;
                        }
                    ls += __shfl_xor_sync(0xffffffffu, ls, 1);
                    ls += __shfl_xor_sync(0xffffffffu, ls, 2);
                    lrow[g] = lrow[g] * corr + ls;
                    mrow[g] = mnew;
#pragma unroll
                    for (int nt = 0; nt < 32; nt++) {
                        out[nt][g*2+0] *= corr;
                        out[nt][g*2+1] *= corr;
                    }
                }
                // pack P -> fp16 A-fragments (hi only)
#pragma unroll
                for (int j = 0; j < 8; j++)
#pragma unroll
                    for (int g = 0; g < 2; g++)
                        ph[j][g] = pack_h2(sacc[j][g*2+0], sacc[j][g*2+1]);
            }

            if (more) { asm volatile("cp.async.wait_group 1;" ::: "memory"); }
            else      { asm volatile("cp.async.wait_group 0;" ::: "memory"); }
            __syncthreads();

            // ---- O += P V (single pass; V in slot1) ----
            if (!skipw) {
#pragma unroll
                for (int s = 0; s < 4; s++) {
                    uint32_t aph[4] = { ph[2*s][0], ph[2*s][1], ph[2*s+1][0], ph[2*s+1][1] };
                    const uint32_t krow = (uint32_t)(s * 16 * QSTR);
#pragma unroll
                    for (int np = 0; np < 16; np++) {
                        uint32_t vf_h[4];
                        const uint32_t vo = krow + (uint32_t)(np * 32) + v_off;
                        ldmatrix_x4_t(vf_h, k1_s + vo);
#pragma unroll
                        for (int u = 0; u < 2; u++) {
                            const int nt = np * 2 + u;
                            mma_f16(out[nt], aph, vf_h[u*2], vf_h[u*2+1]);
                        }
                    }
                }
            }
            __syncthreads();

            if (more) LOAD_TILE(k1_s, klg, ks + 64);
        }
#undef LOAD_TILE

        // ---- epilogue ----
#pragma unroll
        for (int g = 0; g < 2; g++) {
            const float inv = 1.0f / lrow[g];
            const int row = qs + wrow + lg + g * 8;
            __half* oh = g_ao_h + (size_t)(b*SS + row) * QCOLS + h * DD + lc;
#pragma unroll
            for (int nt = 0; nt < 32; nt++) {
                *(uint32_t*)(oh + nt*8) = pack_h2(out[nt][g*2+0] * inv,
                                                  out[nt][g*2+1] * inv);
            }
        }
    }
}

// ---------------------------------------------------------------------------
extern "C" void kernel_launch(void* const* d_in, const int* in_sizes, int n_in,
                              void* d_out, int out_size)
{
    (void)in_sizes; (void)n_in; (void)out_size;
    const float* hidden = (const float*)d_in[0];
    // d_in[1] = attention_mask — analytic, unused
    const float* cosb = (const float*)d_in[2];
    const float* sinb = (const float*)d_in[3];
    const float* Wq = (const float*)d_in[4];
    const float* Wk = (const float*)d_in[5];
    const float* Wv = (const float*)d_in[6];
    const float* Wo = (const float*)d_in[7];
    const float* qw = (const float*)d_in[8];
    const float* kw = (const float*)d_in[9];
    float* out = (float*)d_out;

    float *qp, *kp, *vp;
    cudaGetSymbolAddress((void**)&qp, g_q);
    cudaGetSymbolAddress((void**)&kp, g_k);
    cudaGetSymbolAddress((void**)&vp, g_v);
    __half *hid_h, *hid_l, *wq_h, *wq_l, *wk_h, *wk_l, *wv_h, *wv_l,
           *wo_h, *wo_l, *ao_h;
    cudaGetSymbolAddress((void**)&hid_h, g_hid_h);
    cudaGetSymbolAddress((void**)&hid_l, g_hid_l);
    cudaGetSymbolAddress((void**)&wq_h,  g_wq_h);
    cudaGetSymbolAddress((void**)&wq_l,  g_wq_l);
    cudaGetSymbolAddress((void**)&wk_h,  g_wk_h);
    cudaGetSymbolAddress((void**)&wk_l,  g_wk_l);
    cudaGetSymbolAddress((void**)&wv_h,  g_wv_h);
    cudaGetSymbolAddress((void**)&wv_l,  g_wv_l);
    cudaGetSymbolAddress((void**)&wo_h,  g_wo_h);
    cudaGetSymbolAddress((void**)&wo_l,  g_wo_l);
    cudaGetSymbolAddress((void**)&ao_h,  g_ao_h);

    cudaFuncSetAttribute(gemm_qkv, cudaFuncAttributeMaxDynamicSharedMemorySize, QKV_SMEM);
    cudaFuncSetAttribute(gemm_wo,  cudaFuncAttributeMaxDynamicSharedMemorySize, WO_SMEM);
    cudaFuncSetAttribute(attn_hmma, cudaFuncAttributeMaxDynamicSharedMemorySize, ATT_SMEM);

    // 0) ONE merged split launch: all fp32 -> fp16 hi/lo conversions
    split_all<<<SPLIT_BLOCKS, 256>>>(hidden, Wq, Wk, Wv, Wo,
                                     hid_h, hid_l, wq_h, wq_l,
                                     wk_h, wk_l, wv_h, wv_l, wo_h, wo_l);

    // 1) fused QKV projection (3-pass, 2-stage, occ-2)
    gemm_qkv<<<dim3(32, 32), 256, QKV_SMEM>>>(
        hid_h, hid_l, wq_h, wq_l, wk_h, wk_l, wv_h, wv_l, qp, kp, vp);

    // 2) RMSNorm + RoPE (warp-per-row) -> fp16 hi/lo; resets work counter
    rmsrope_kernel<<<MROWS * 16 / 8, 256>>>(cosb, sinb, qw, kw);

    // 3) persistent HMMA sliding-window flash attention -> fp16 ao
    attn_hmma<<<152, 256, ATT_SMEM>>>();

    // 4) output projection (1-pass, 2-stage) -> fp32 d_out
    gemm_wo<<<dim3(HH/128, MROWS/128), 256, WO_SMEM>>>(ao_h, wo_h, out);
}

// round 14
// speedup vs baseline: 1.1941x; 1.0086x over previous
#include <cuda_runtime.h>
#include <cuda_fp16.h>
#include <cstdint>
#include <math.h>

// Problem constants
#define BB    2
#define SS    2048
#define HH    2560
#define NHQ   8
#define NKV   4
#define DD    256
#define SWIN  1024
#define MROWS (BB*SS)          // 4096
#define QCOLS (NHQ*DD)         // 2048
#define KVCOLS (NKV*DD)        // 1024

// ---------------- scratch (allocation-free rule: device globals) ------------
__device__ float g_q [ (size_t)MROWS * QCOLS ];
__device__ float g_k [ (size_t)MROWS * KVCOLS ];
__device__ float g_v [ (size_t)MROWS * KVCOLS ];
__device__ int   g_work_ctr;      // attention queue
__device__ int   g_work_ctr2;     // QKV queue

// split-fp16 operands
__device__ __half g_hid_h[(size_t)MROWS*HH],  g_hid_l[(size_t)MROWS*HH];
__device__ __half g_wq_h [(size_t)QCOLS*HH],  g_wq_l [(size_t)QCOLS*HH];
__device__ __half g_wk_h [(size_t)KVCOLS*HH], g_wk_l [(size_t)KVCOLS*HH];
__device__ __half g_wv_h [(size_t)KVCOLS*HH], g_wv_l [(size_t)KVCOLS*HH];
__device__ __half g_wo_h [(size_t)HH*QCOLS],  g_wo_l [(size_t)HH*QCOLS];
// post-rmsnorm/rope q/k (hi/lo) and v (hi only)
__device__ __half g_qh[(size_t)MROWS*QCOLS],  g_ql[(size_t)MROWS*QCOLS];
__device__ __half g_kh[(size_t)MROWS*KVCOLS], g_kl[(size_t)MROWS*KVCOLS];
__device__ __half g_vh[(size_t)MROWS*KVCOLS];
// attention output (hi only)
__device__ __half g_ao_h[(size_t)MROWS*QCOLS];

// ---------------- helpers ----------------------------------------------------
__device__ __forceinline__ uint32_t smem_u32(const void* p) {
    uint32_t a;
    asm("{ .reg .u64 t; cvta.to.shared.u64 t, %1; cvt.u32.u64 %0, t; }"
        : "=r"(a) : "l"(p));
    return a;
}
__device__ __forceinline__ void ldmatrix_x4(uint32_t* r, uint32_t addr) {
    asm volatile("ldmatrix.sync.aligned.m8n8.x4.shared.b16 {%0,%1,%2,%3}, [%4];"
                 : "=r"(r[0]), "=r"(r[1]), "=r"(r[2]), "=r"(r[3]) : "r"(addr));
}
__device__ __forceinline__ void ldmatrix_x4_t(uint32_t* r, uint32_t addr) {
    asm volatile("ldmatrix.sync.aligned.m8n8.x4.trans.shared.b16 {%0,%1,%2,%3}, [%4];"
                 : "=r"(r[0]), "=r"(r[1]), "=r"(r[2]), "=r"(r[3]) : "r"(addr));
}
__device__ __forceinline__ void mma_f16(float* d, const uint32_t* a,
                                        uint32_t b0, uint32_t b1) {
    asm volatile(
        "mma.sync.aligned.m16n8k16.row.col.f32.f16.f16.f32 "
        "{%0,%1,%2,%3}, {%4,%5,%6,%7}, {%8,%9}, {%0,%1,%2,%3};"
        : "+f"(d[0]), "+f"(d[1]), "+f"(d[2]), "+f"(d[3])
        : "r"(a[0]), "r"(a[1]), "r"(a[2]), "r"(a[3]), "r"(b0), "r"(b1));
}
__device__ __forceinline__ void cp_async16(uint32_t saddr, const void* gaddr) {
    asm volatile("cp.async.cg.shared.global [%0], [%1], 16;"
                 :: "r"(saddr), "l"(gaddr));
}
__device__ __forceinline__ uint32_t pack_h2(float a, float b) {
    __half2 t; t.x = __float2half(a); t.y = __float2half(b);
    return *(uint32_t*)&t;
}

// ---------------------------------------------------------------------------
// Merged split kernel (also resets QKV work counter).
// ---------------------------------------------------------------------------
#define SPLIT_BLOCKS 25600

__global__ void __launch_bounds__(256) split_all(
    const float* __restrict__ hid, const float* __restrict__ wq,
    const float* __restrict__ wk,  const float* __restrict__ wv,
    const float* __restrict__ wo,
    __half* __restrict__ hid_h, __half* __restrict__ hid_l,
    __half* __restrict__ wq_h,  __half* __restrict__ wq_l,
    __half* __restrict__ wk_h,  __half* __restrict__ wk_l,
    __half* __restrict__ wv_h,  __half* __restrict__ wv_l,
    __half* __restrict__ wo_h,  __half* __restrict__ wo_l)
{
    if (blockIdx.x == 0 && threadIdx.x == 0) g_work_ctr2 = 0;

    const int b = blockIdx.x;
    const float* src;
    __half *hi, *lo;
    int i;
    if (b < 10240)      { src = hid; hi = hid_h; lo = hid_l; i = b * 256 + threadIdx.x; }
    else if (b < 15360) { src = wq;  hi = wq_h;  lo = wq_l;  i = (b - 10240) * 256 + threadIdx.x; }
    else if (b < 17920) { src = wk;  hi = wk_h;  lo = wk_l;  i = (b - 15360) * 256 + threadIdx.x; }
    else if (b < 20480) { src = wv;  hi = wv_h;  lo = wv_l;  i = (b - 17920) * 256 + threadIdx.x; }
    else                { src = wo;  hi = wo_h;  lo = wo_l;  i = (b - 20480) * 256 + threadIdx.x; }

    float4 v = ((const float4*)src)[i];
    __half hx = __float2half(v.x), hy = __float2half(v.y);
    __half hz = __float2half(v.z), hw = __float2half(v.w);
    __half lx = __float2half(v.x - __half2float(hx));
    __half ly = __float2half(v.y - __half2float(hy));
    __half lz = __float2half(v.z - __half2float(hz));
    __half lw = __float2half(v.w - __half2float(hw));
    __half2 h01; h01.x = hx; h01.y = hy;
    __half2 h23; h23.x = hz; h23.y = hw;
    __half2 l01; l01.x = lx; l01.y = ly;
    __half2 l23; l23.x = lz; l23.y = lw;
    ((__half2*)hi)[2*i]   = h01;
    ((__half2*)hi)[2*i+1] = h23;
    ((__half2*)lo)[2*i]   = l01;
    ((__half2*)lo)[2*i+1] = l23;
}

// ---------------------------------------------------------------------------
// QKV projection — PERSISTENT, heterogeneous passes.
// Items 0..767: q/k tiles (3-pass).  Items 768..1023: v tiles (2-pass).
// Tile body is a template so each variant has a branch-free unrolled core.
// 80KB smem, __launch_bounds__(256,2) -> 2 CTAs/SM.
// ---------------------------------------------------------------------------
#define PADK   40
#define TILE_B (128 * PADK * 2)
#define STAGE3_B (4 * TILE_B)       // 40960
#define QKV_SMEM (2 * STAGE3_B)     // 81920
#define NWORK_G 1024

template <bool THREE>
__device__ __forceinline__ void qkv_tile(
    uint32_t sbase, int tid, int wid, int lane,
    const __half* __restrict__ Ah, const __half* __restrict__ Al,
    const __half* __restrict__ Bh, const __half* __restrict__ Bl,
    float* __restrict__ C, int m0, int n0, int NN)
{
    const int K = HH;
    const int wm = wid >> 2;
    const int wn = wid & 3;

    const __half* gb[4] = {
        Ah + (size_t)m0 * K, Al + (size_t)m0 * K,
        Bh + (size_t)n0 * K, Bl + (size_t)n0 * K };

    const int NC = K >> 5;

#define ISSUE3(c, s) do {                                                     \
    _Pragma("unroll")                                                         \
    for (int i = 0; i < 8; i++) {                                             \
        int e    = tid + i * 256;                                             \
        int t    = e >> 9;                                                    \
        int rem  = e & 511;                                                   \
        int row  = rem >> 2;                                                  \
        int c16  = rem & 3;                                                   \
        uint32_t sa = sbase + (s) * STAGE3_B + t * TILE_B + row * (PADK*2) + c16 * 16; \
        cp_async16(sa, gb[t] + (size_t)row * K + (c) * 32 + c16 * 8);         \
    }                                                                         \
    asm volatile("cp.async.commit_group;" ::: "memory");                      \
} while (0)

    float acc[4][4][4];
#pragma unroll
    for (int i = 0; i < 4; i++)
#pragma unroll
        for (int j = 0; j < 4; j++)
#pragma unroll
            for (int r = 0; r < 4; r++) acc[i][j][r] = 0.f;

    const uint32_t a_off = (uint32_t)((lane & 15) * (PADK*2) + (lane >> 4) * 16);
    const uint32_t b_off = (uint32_t)(((lane & 7) + ((lane >> 4) << 3)) * (PADK*2)
                                      + ((lane >> 3) & 1) * 16);

    ISSUE3(0, 0);

    for (int c = 0; c < NC; c++) {
        const int s = c & 1;
        if (c + 1 < NC) {
            ISSUE3(c + 1, (c + 1) & 1);
            asm volatile("cp.async.wait_group 1;" ::: "memory");
        } else {
            asm volatile("cp.async.wait_group 0;" ::: "memory");
        }
        __syncthreads();

        const uint32_t sAh = sbase + s * STAGE3_B;
        const uint32_t sAl = sAh + TILE_B;
        const uint32_t sBh = sAh + 2 * TILE_B;
        const uint32_t sBl = sAh + 3 * TILE_B;

#pragma unroll
        for (int ks = 0; ks < 2; ks++) {
            const uint32_t kbyte = (uint32_t)(ks * 32);

            uint32_t ah[4][4], al[4][4];
#pragma unroll
            for (int i = 0; i < 4; i++) {
                const uint32_t ro = (uint32_t)((wm * 64 + i * 16) * (PADK*2)) + kbyte;
                ldmatrix_x4(ah[i], sAh + ro + a_off);
                if (THREE) ldmatrix_x4(al[i], sAl + ro + a_off);
            }
            uint32_t bh[2][4], bl[2][4];
#pragma unroll
            for (int p = 0; p < 2; p++) {
                const uint32_t ro = (uint32_t)((wn * 32 + p * 16) * (PADK*2)) + kbyte;
                ldmatrix_x4(bh[p], sBh + ro + b_off);
                ldmatrix_x4(bl[p], sBl + ro + b_off);
            }
#pragma unroll
            for (int i = 0; i < 4; i++)
#pragma unroll
                for (int j = 0; j < 4; j++) {
                    const int p = j >> 1, u = (j & 1) * 2;
                    mma_f16(acc[i][j], ah[i], bh[p][u], bh[p][u+1]);
                    mma_f16(acc[i][j], ah[i], bl[p][u], bl[p][u+1]);
                    if (THREE)
                        mma_f16(acc[i][j], al[i], bh[p][u], bh[p][u+1]);
                }
        }
        __syncthreads();
    }
#undef ISSUE3

    const int rbase = m0 + wm * 64 + (lane >> 2);
    const int cbase = n0 + wn * 32 + (lane & 3) * 2;
#pragma unroll
    for (int i = 0; i < 4; i++)
#pragma unroll
        for (int j = 0; j < 4; j++) {
            float* p0 = C + (size_t)(rbase + i * 16) * NN + cbase + j * 8;
            float* p1 = p0 + 8 * (size_t)NN;
            *(float2*)p0 = make_float2(acc[i][j][0], acc[i][j][1]);
            *(float2*)p1 = make_float2(acc[i][j][2], acc[i][j][3]);
        }
}

__global__ void __launch_bounds__(256, 2) gemm_qkv(
    const __half* __restrict__ Ah, const __half* __restrict__ Al,
    const __half* __restrict__ wqh, const __half* __restrict__ wql,
    const __half* __restrict__ wkh, const __half* __restrict__ wkl,
    const __half* __restrict__ wvh, const __half* __restrict__ wvl,
    float* __restrict__ qout, float* __restrict__ kout, float* __restrict__ vout)
{
    extern __shared__ char smem[];
    const uint32_t sbase = smem_u32(smem);
    const int tid  = threadIdx.x;
    const int wid  = tid >> 5, lane = tid & 31;

    __shared__ int s_item;

    for (;;) {
        __syncthreads();
        if (tid == 0) s_item = atomicAdd(&g_work_ctr2, 1);
        __syncthreads();
        const int item = s_item;
        if (item >= NWORK_G) break;

        if (item < 768) {
            // q/k tiles: ix 0..23, iy 0..31
            const int ix = item >> 5;
            const int iy = item & 31;
            const int n0g = ix * 128;
            const int m0  = iy * 128;
            if (n0g < QCOLS)
                qkv_tile<true>(sbase, tid, wid, lane, Ah, Al, wqh, wql,
                               qout, m0, n0g, QCOLS);
            else
                qkv_tile<true>(sbase, tid, wid, lane, Ah, Al, wkh, wkl,
                               kout, m0, n0g - QCOLS, KVCOLS);
        } else {
            const int idx = item - 768;
            const int ix = idx >> 5;          // 0..7
            const int iy = idx & 31;
            qkv_tile<false>(sbase, tid, wid, lane, Ah, Al, wvh, wvl,
                            vout, iy * 128, ix * 128, KVCOLS);
        }
    }
}

// ---------------------------------------------------------------------------
// Output projection, 1-PASS fp16 HMMA, 2-stage pipeline.
// ---------------------------------------------------------------------------
#define STAGE1_B (2 * TILE_B)       // 20480
#define WO_SMEM (2 * STAGE1_B)      // 40960

__global__ void __launch_bounds__(256) gemm_wo(
    const __half* __restrict__ Ah,
    const __half* __restrict__ Bh,
    float* __restrict__ C)
{
    extern __shared__ char smem[];
    const uint32_t sbase = smem_u32(smem);
    const int K = QCOLS, NN = HH;

    const int tid  = threadIdx.x;
    const int wid  = tid >> 5, lane = tid & 31;
    const int wm   = wid >> 2;
    const int wn   = wid & 3;
    const int m0   = blockIdx.y * 128, n0 = blockIdx.x * 128;

    const __half* gb[2] = { Ah + (size_t)m0 * K, Bh + (size_t)n0 * K };

    const int NC = K >> 5;

#define ISSUE1(c, s) do {                                                     \
    _Pragma("unroll")                                                         \
    for (int i = 0; i < 4; i++) {                                             \
        int e    = tid + i * 256;                                             \
        int t    = e >> 9;                                                    \
        int rem  = e & 511;                                                   \
        int row  = rem >> 2;                                                  \
        int c16  = rem & 3;                                                   \
        uint32_t sa = sbase + (s) * STAGE1_B + t * TILE_B + row * (PADK*2) + c16 * 16; \
        cp_async16(sa, gb[t] + (size_t)row * K + (c) * 32 + c16 * 8);         \
    }                                                                         \
    asm volatile("cp.async.commit_group;" ::: "memory");                      \
} while (0)

    float acc[4][4][4];
#pragma unroll
    for (int i = 0; i < 4; i++)
#pragma unroll
        for (int j = 0; j < 4; j++)
#pragma unroll
            for (int r = 0; r < 4; r++) acc[i][j][r] = 0.f;

    const uint32_t a_off = (uint32_t)((lane & 15) * (PADK*2) + (lane >> 4) * 16);
    const uint32_t b_off = (uint32_t)(((lane & 7) + ((lane >> 4) << 3)) * (PADK*2)
                                      + ((lane >> 3) & 1) * 16);

    ISSUE1(0, 0);

    for (int c = 0; c < NC; c++) {
        const int s = c & 1;
        if (c + 1 < NC) {
            ISSUE1(c + 1, (c + 1) & 1);
            asm volatile("cp.async.wait_group 1;" ::: "memory");
        } else {
            asm volatile("cp.async.wait_group 0;" ::: "memory");
        }
        __syncthreads();

        const uint32_t sAh = sbase + s * STAGE1_B;
        const uint32_t sBh = sAh + TILE_B;

#pragma unroll
        for (int ks = 0; ks < 2; ks++) {
            const uint32_t kbyte = (uint32_t)(ks * 32);

            uint32_t ah[4][4];
#pragma unroll
            for (int i = 0; i < 4; i++) {
                const uint32_t ro = (uint32_t)((wm * 64 + i * 16) * (PADK*2)) + kbyte;
                ldmatrix_x4(ah[i], sAh + ro + a_off);
            }
            uint32_t bh[2][4];
#pragma unroll
            for (int p = 0; p < 2; p++) {
                const uint32_t ro = (uint32_t)((wn * 32 + p * 16) * (PADK*2)) + kbyte;
                ldmatrix_x4(bh[p], sBh + ro + b_off);
            }
#pragma unroll
            for (int i = 0; i < 4; i++)
#pragma unroll
                for (int j = 0; j < 4; j++) {
                    const int p = j >> 1, u = (j & 1) * 2;
                    mma_f16(acc[i][j], ah[i], bh[p][u], bh[p][u+1]);
                }
        }
        __syncthreads();
    }
#undef ISSUE1

    const int rbase = m0 + wm * 64 + (lane >> 2);
    const int cbase = n0 + wn * 32 + (lane & 3) * 2;
#pragma unroll
    for (int i = 0; i < 4; i++)
#pragma unroll
        for (int j = 0; j < 4; j++) {
            float* p0 = C + (size_t)(rbase + i * 16) * NN + cbase + j * 8;
            float* p1 = p0 + 8 * (size_t)NN;
            *(float2*)p0 = make_float2(acc[i][j][0], acc[i][j][1]);
            *(float2*)p1 = make_float2(acc[i][j][2], acc[i][j][3]);
        }
}

// ---------------------------------------------------------------------------
// RMSNorm (+ optional weight) + RoPE — warp-per-(row,head); resets attn ctr.
// ---------------------------------------------------------------------------
__global__ void __launch_bounds__(256) rmsrope_kernel(
    const float* __restrict__ cosb, const float* __restrict__ sinb,
    const float* __restrict__ qw,  const float* __restrict__ kw)
{
    if (blockIdx.x == 0 && threadIdx.x == 0) g_work_ctr = 0;

    const int gw   = blockIdx.x * 8 + (threadIdx.x >> 5);
    const int row  = gw >> 4;
    const int part = gw & 15;
    const int lane = threadIdx.x & 31;
    const int d0   = lane * 4;

    const float* ptr;
    __half *hp, *lp = nullptr;
    const float* w = nullptr;
    bool do_rope = true;
    if (part < 8) {
        size_t off = (size_t)row * QCOLS + part * DD;
        ptr = g_q + off; hp = g_qh + off; lp = g_ql + off; w = qw;
    } else if (part < 12) {
        size_t off = (size_t)row * KVCOLS + (part - 8) * DD;
        ptr = g_k + off; hp = g_kh + off; lp = g_kl + off; w = kw;
    } else {
        size_t off = (size_t)row * KVCOLS + (part - 12) * DD;
        ptr = g_v + off; hp = g_vh + off; do_rope = false;
    }

    float4 x1 = *(const float4*)(ptr + d0);
    float4 x2 = *(const float4*)(ptr + 128 + d0);
    float ss = x1.x*x1.x + x1.y*x1.y + x1.z*x1.z + x1.w*x1.w
             + x2.x*x2.x + x2.y*x2.y + x2.z*x2.z + x2.w*x2.w;
#pragma unroll
    for (int o = 16; o; o >>= 1) ss += __shfl_xor_sync(0xffffffffu, ss, o);
    const float inv = rsqrtf(ss * (1.0f / DD) + 1e-6f);

    float y1[4] = { x1.x*inv, x1.y*inv, x1.z*inv, x1.w*inv };
    float y2[4] = { x2.x*inv, x2.y*inv, x2.z*inv, x2.w*inv };

    if (w) {
        float4 w1 = *(const float4*)(w + d0);
        float4 w2 = *(const float4*)(w + 128 + d0);
        y1[0] *= 1.f + w1.x; y1[1] *= 1.f + w1.y;
        y1[2] *= 1.f + w1.z; y1[3] *= 1.f + w1.w;
        y2[0] *= 1.f + w2.x; y2[1] *= 1.f + w2.y;
        y2[2] *= 1.f + w2.z; y2[3] *= 1.f + w2.w;
    }

    float o1[4], o2[4];
    if (do_rope) {
        const int s = row & (SS - 1);
        const float* cb = cosb + (size_t)s * DD;
        const float* sb = sinb + (size_t)s * DD;
        float4 c1 = *(const float4*)(cb + d0);
        float4 s1 = *(const float4*)(sb + d0);
        float4 c2 = *(const float4*)(cb + 128 + d0);
        float4 s2 = *(const float4*)(sb + 128 + d0);
        o1[0] = y1[0]*c1.x - y2[0]*s1.x;  o1[1] = y1[1]*c1.y - y2[1]*s1.y;
        o1[2] = y1[2]*c1.z - y2[2]*s1.z;  o1[3] = y1[3]*c1.w - y2[3]*s1.w;
        o2[0] = y2[0]*c2.x + y1[0]*s2.x;  o2[1] = y2[1]*c2.y + y1[1]*s2.y;
        o2[2] = y2[2]*c2.z + y1[2]*s2.z;  o2[3] = y2[3]*c2.w + y1[3]*s2.w;
    } else {
#pragma unroll
        for (int i = 0; i < 4; i++) { o1[i] = y1[i]; o2[i] = y2[i]; }
    }

    uint2 h1, h2;
    h1.x = pack_h2(o1[0], o1[1]); h1.y = pack_h2(o1[2], o1[3]);
    h2.x = pack_h2(o2[0], o2[1]); h2.y = pack_h2(o2[2], o2[3]);
    *(uint2*)(hp + d0)       = h1;
    *(uint2*)(hp + 128 + d0) = h2;
    if (lp) {
        __half q10 = __float2half(o1[0]), q11 = __float2half(o1[1]);
        __half q12 = __float2half(o1[2]), q13 = __float2half(o1[3]);
        __half q20 = __float2half(o2[0]), q21 = __float2half(o2[1]);
        __half q22 = __float2half(o2[2]), q23 = __float2half(o2[3]);
        uint2 l1, l2;
        l1.x = pack_h2(o1[0] - __half2float(q10), o1[1] - __half2float(q11));
        l1.y = pack_h2(o1[2] - __half2float(q12), o1[3] - __half2float(q13));
        l2.x = pack_h2(o2[0] - __half2float(q20), o2[1] - __half2float(q21));
        l2.y = pack_h2(o2[2] - __half2float(q22), o2[3] - __half2float(q23));
        *(uint2*)(lp + d0)       = l1;
        *(uint2*)(lp + 128 + d0) = l2;
    }
}

// ---------------------------------------------------------------------------
// HMMA split-fp16 sliding-window flash attention — persistent work queue.
// QK^T: 3-pass. PV: single pass. Per-warp full-mask tile skip (exact).
// ---------------------------------------------------------------------------
#define QSTR 528
#define QTILE (128 * QSTR)
#define KTILE (64 * QSTR)
#define ATT_SMEM (2*QTILE + 2*KTILE) // 202752
#define NWORK (16 * NHQ * BB)        // 256 work items

__global__ void __launch_bounds__(256, 1) attn_hmma()
{
    extern __shared__ char smem[];
    const uint32_t sb   = smem_u32(smem);
    const uint32_t qh_s = sb;
    const uint32_t ql_s = sb + QTILE;
    const uint32_t k0_s = sb + 2 * QTILE;
    const uint32_t k1_s = k0_s + KTILE;

    const int tid  = threadIdx.x;
    const int wid  = tid >> 5, lane = tid & 31;
    const int wrow = wid * 16;

    __shared__ int s_item;

    const uint32_t a_off = (uint32_t)((wrow + (lane & 15)) * QSTR + (lane >> 4) * 16);
    const uint32_t b_off = (uint32_t)(((lane & 7) + ((lane >> 4) << 3)) * QSTR
                                      + ((lane >> 3) & 1) * 16);
    const uint32_t v_off = (uint32_t)((lane & 15) * QSTR + (lane >> 4) * 16);
    const int lg = lane >> 2;
    const int lc = (lane & 3) * 2;

    for (;;) {
        __syncthreads();
        if (tid == 0) s_item = atomicAdd(&g_work_ctr, 1);
        __syncthreads();
        const int item = s_item;
        if (item >= NWORK) break;

        const int rrr  = item >> 4;
        const int bh   = item & 15;
        const int qblk = 15 - rrr;
        const int h    = bh & 7;
        const int b    = bh >> 3;
        const int kvh  = h >> 1;
        const int qs   = qblk * 128;
        const int qlo  = qs + wrow;

        {
            const __half* qsrc[2] = {
                g_qh + (size_t)(b*SS + qs) * QCOLS + h * DD,
                g_ql + (size_t)(b*SS + qs) * QCOLS + h * DD };
#pragma unroll
            for (int i = 0; i < 32; i++) {
                int e = tid + i * 256;
                int arr = e >> 12;
                int rem = e & 4095;
                int row = rem >> 5, c16 = rem & 31;
                cp_async16((arr ? ql_s : qh_s) + row * QSTR + c16 * 16,
                           qsrc[arr] + (size_t)row * QCOLS + c16 * 8);
            }
            asm volatile("cp.async.commit_group;" ::: "memory");
        }

        float out[32][4];
#pragma unroll
        for (int nt = 0; nt < 32; nt++)
#pragma unroll
            for (int r = 0; r < 4; r++) out[nt][r] = 0.f;
        float mrow[2] = {-1e30f, -1e30f};
        float lrow[2] = {0.f, 0.f};

        const __half* khg = g_kh + (size_t)(b*SS) * KVCOLS + kvh * DD;
        const __half* klg = g_kl + (size_t)(b*SS) * KVCOLS + kvh * DD;
        const __half* vhg = g_vh + (size_t)(b*SS) * KVCOLS + kvh * DD;

        int ksmin = qs - (SWIN - 1);
        if (ksmin < 0) ksmin = 0;
        const int t0 = ksmin >> 6;
        const int t1 = (qs + 127) >> 6;

#define LOAD_TILE(dst, src, ks_) do {                                          \
    _Pragma("unroll")                                                          \
    for (int i = 0; i < 8; i++) {                                              \
        int e = tid + i * 256;                                                 \
        int row = e >> 5, c16 = e & 31;                                        \
        cp_async16((dst) + row * QSTR + c16 * 16,                              \
                   (src) + (size_t)((ks_) + row) * KVCOLS + c16 * 8);          \
    }                                                                          \
    asm volatile("cp.async.commit_group;" ::: "memory");                       \
} while (0)

        LOAD_TILE(k0_s, khg, t0 << 6);
        LOAD_TILE(k1_s, klg, t0 << 6);

        for (int kt = t0; kt <= t1; kt++) {
            const int ks = kt << 6;
            const bool more = (kt < t1);
            const bool skipw = ((qlo + 15) < ks) || ((ks + 63) <= (qlo - SWIN));

            asm volatile("cp.async.wait_group 0;" ::: "memory");
            __syncthreads();

            float sacc[8][4];
            uint32_t ph[8][2];
            if (!skipw) {
#pragma unroll
                for (int j = 0; j < 8; j++)
#pragma unroll
                    for (int r = 0; r < 4; r++) sacc[j][r] = 0.f;

#pragma unroll
                for (int ks16 = 0; ks16 < 16; ks16++) {
                    uint32_t qf_h[4], qf_l[4];
                    ldmatrix_x4(qf_h, qh_s + a_off + ks16 * 32);
                    ldmatrix_x4(qf_l, ql_s + a_off + ks16 * 32);
#pragma unroll
                    for (int jp = 0; jp < 4; jp++) {
                        uint32_t kf_h[4], kf_l[4];
                        const uint32_t ro = (uint32_t)(jp * 16 * QSTR) + ks16 * 32;
                        ldmatrix_x4(kf_h, k0_s + ro + b_off);
                        ldmatrix_x4(kf_l, k1_s + ro + b_off);
#pragma unroll
                        for (int u = 0; u < 2; u++) {
                            const int j = jp * 2 + u;
                            mma_f16(sacc[j], qf_h, kf_h[u*2], kf_h[u*2+1]);
                            mma_f16(sacc[j], qf_h, kf_l[u*2], kf_l[u*2+1]);
                            mma_f16(sacc[j], qf_l, kf_h[u*2], kf_h[u*2+1]);
                        }
                    }
                }
            }
            __syncthreads();

            LOAD_TILE(k1_s, vhg, ks);
            if (more) LOAD_TILE(k0_s, khg, ks + 64);

            if (!skipw) {
#pragma unroll
                for (int g = 0; g < 2; g++) {
                    const int qi = qs + wrow + lg + g * 8;
                    float mloc = -1e30f;
#pragma unroll
                    for (int j = 0; j < 8; j++)
#pragma unroll
                        for (int e = 0; e < 2; e++) {
                            const int kj = ks + j * 8 + lc + e;
                            float s = sacc[j][g*2+e];
                            if (kj > qi || kj <= qi - SWIN) s = -1e30f;
                            sacc[j][g*2+e] = s;
                            mloc = fmaxf(mloc, s);
                        }
                    mloc = fmaxf(mloc, __shfl_xor_sync(0xffffffffu, mloc, 1));
                    mloc = fmaxf(mloc, __shfl_xor_sync(0xffffffffu, mloc, 2));
                    const float mnew = fmaxf(mrow[g], mloc);
                    const float corr = __expf(mrow[g] - mnew);
                    float ls = 0.f;
#pragma unroll
                    for (int j = 0; j < 8; j++)
#pragma unroll
                        for (int e = 0; e < 2; e++) {
                            float s = sacc[j][g*2+e];
                            float p = (s <= -1e29f) ? 0.f : __expf(s - mnew);
                            sacc[j][g*2+e] = p;
                            ls += p;
                        }
                    ls += __shfl_xor_sync(0xffffffffu, ls, 1);
                    ls += __shfl_xor_sync(0xffffffffu, ls, 2);
                    lrow[g] = lrow[g] * corr + ls;
                    mrow[g] = mnew;
#pragma unroll
                    for (int nt = 0; nt < 32; nt++) {
                        out[nt][g*2+0] *= corr;
                        out[nt][g*2+1] *= corr;
                    }
                }
#pragma unroll
                for (int j = 0; j < 8; j++)
#pragma unroll
                    for (int g = 0; g < 2; g++)
                        ph[j][g] = pack_h2(sacc[j][g*2+0], sacc[j][g*2+1]);
            }

            if (more) { asm volatile("cp.async.wait_group 1;" ::: "memory"); }
            else      { asm volatile("cp.async.wait_group 0;" ::: "memory"); }
            __syncthreads();

            if (!skipw) {
#pragma unroll
                for (int s = 0; s < 4; s++) {
                    uint32_t aph[4] = { ph[2*s][0], ph[2*s][1], ph[2*s+1][0], ph[2*s+1][1] };
                    const uint32_t krow = (uint32_t)(s * 16 * QSTR);
#pragma unroll
                    for (int np = 0; np < 16; np++) {
                        uint32_t vf_h[4];
                        const uint32_t vo = krow + (uint32_t)(np * 32) + v_off;
                        ldmatrix_x4_t(vf_h, k1_s + vo);
#pragma unroll
                        for (int u = 0; u < 2; u++) {
                            const int nt = np * 2 + u;
                            mma_f16(out[nt], aph, vf_h[u*2], vf_h[u*2+1]);
                        }
                    }
                }
            }
            __syncthreads();

            if (more) LOAD_TILE(k1_s, klg, ks + 64);
        }
#undef LOAD_TILE

#pragma unroll
        for (int g = 0; g < 2; g++) {
            const float inv = 1.0f / lrow[g];
            const int row = qs + wrow + lg + g * 8;
            __half* oh = g_ao_h + (size_t)(b*SS + row) * QCOLS + h * DD + lc;
#pragma unroll
            for (int nt = 0; nt < 32; nt++) {
                *(uint32_t*)(oh + nt*8) = pack_h2(out[nt][g*2+0] * inv,
                                                  out[nt][g*2+1] * inv);
            }
        }
    }
}

// ---------------------------------------------------------------------------
extern "C" void kernel_launch(void* const* d_in, const int* in_sizes, int n_in,
                              void* d_out, int out_size)
{
    (void)in_sizes; (void)n_in; (void)out_size;
    const float* hidden = (const float*)d_in[0];
    // d_in[1] = attention_mask — analytic, unused
    const float* cosb = (const float*)d_in[2];
    const float* sinb = (const float*)d_in[3];
    const float* Wq = (const float*)d_in[4];
    const float* Wk = (const float*)d_in[5];
    const float* Wv = (const float*)d_in[6];
    const float* Wo = (const float*)d_in[7];
    const float* qw = (const float*)d_in[8];
    const float* kw = (const float*)d_in[9];
    float* out = (float*)d_out;

    float *qp, *kp, *vp;
    cudaGetSymbolAddress((void**)&qp, g_q);
    cudaGetSymbolAddress((void**)&kp, g_k);
    cudaGetSymbolAddress((void**)&vp, g_v);
    __half *hid_h, *hid_l, *wq_h, *wq_l, *wk_h, *wk_l, *wv_h, *wv_l,
           *wo_h, *wo_l, *ao_h;
    cudaGetSymbolAddress((void**)&hid_h, g_hid_h);
    cudaGetSymbolAddress((void**)&hid_l, g_hid_l);
    cudaGetSymbolAddress((void**)&wq_h,  g_wq_h);
    cudaGetSymbolAddress((void**)&wq_l,  g_wq_l);
    cudaGetSymbolAddress((void**)&wk_h,  g_wk_h);
    cudaGetSymbolAddress((void**)&wk_l,  g_wk_l);
    cudaGetSymbolAddress((void**)&wv_h,  g_wv_h);
    cudaGetSymbolAddress((void**)&wv_l,  g_wv_l);
    cudaGetSymbolAddress((void**)&wo_h,  g_wo_h);
    cudaGetSymbolAddress((void**)&wo_l,  g_wo_l);
    cudaGetSymbolAddress((void**)&ao_h,  g_ao_h);

    cudaFuncSetAttribute(gemm_qkv, cudaFuncAttributeMaxDynamicSharedMemorySize, QKV_SMEM);
    cudaFuncSetAttribute(gemm_wo,  cudaFuncAttributeMaxDynamicSharedMemorySize, WO_SMEM);
    cudaFuncSetAttribute(attn_hmma, cudaFuncAttributeMaxDynamicSharedMemorySize, ATT_SMEM);

    // 0) merged split (also resets QKV queue counter)
    split_all<<<SPLIT_BLOCKS, 256>>>(hidden, Wq, Wk, Wv, Wo,
                                     hid_h, hid_l, wq_h, wq_l,
                                     wk_h, wk_l, wv_h, wv_l, wo_h, wo_l);

    // 1) persistent QKV projection (q/k 3-pass first, v 2-pass after)
    gemm_qkv<<<296, 256, QKV_SMEM>>>(
        hid_h, hid_l, wq_h, wq_l, wk_h, wk_l, wv_h, wv_l, qp, kp, vp);

    // 2) RMSNorm + RoPE (warp-per-row) -> fp16 hi/lo; resets attn counter
    rmsrope_kernel<<<MROWS * 16 / 8, 256>>>(cosb, sinb, qw, kw);

    // 3) persistent HMMA sliding-window flash attention -> fp16 ao
    attn_hmma<<<152, 256, ATT_SMEM>>>();

    // 4) output projection (1-pass, 2-stage) -> fp32 d_out
    gemm_wo<<<dim3(HH/128, MROWS/128), 256, WO_SMEM>>>(ao_h, wo_h, out);
}